// round 2
// baseline (speedup 1.0000x reference)
#include <cuda_runtime.h>
#include <cuda_bf16.h>

// Problem constants
#define N_ATOMS   50000
#define N_PAIRS   1600000
#define NF        128     // basis == filters == 128
#define N_RBF     20
#define E_TILE    128
#define N_TILES   (N_PAIRS / E_TILE)   // 12500 exactly
#define LOG2F_C   0.69314718055994530942f

typedef unsigned long long u64;

// ---------------- scratch (no cudaMalloc allowed) ----------------
__device__ float g_h[N_ATOMS * NF];
__device__ float g_agg[N_ATOMS * NF];

// ---------------- f32x2 packed math helpers ----------------
__device__ __forceinline__ u64 pack2(float x) {
    u64 d; unsigned v = __float_as_uint(x);
    asm("mov.b64 %0, {%1, %1};" : "=l"(d) : "r"(v));
    return d;
}
__device__ __forceinline__ void fma2(u64& d, u64 a, u64 b) {
    asm("fma.rn.f32x2 %0, %1, %2, %0;" : "+l"(d) : "l"(a), "l"(b));
}
__device__ __forceinline__ float2 unpack2(u64 d) {
    unsigned lo, hi;
    asm("mov.b64 {%0, %1}, %2;" : "=r"(lo), "=r"(hi) : "l"(d));
    return make_float2(__uint_as_float(lo), __uint_as_float(hi));
}

__device__ __forceinline__ float sspf(float x) {
    // softplus(x) - log(2), stable for |x| large
    float e = __expf(-fabsf(x));
    return fmaxf(x, 0.0f) + __logf(1.0f + e) - LOG2F_C;
}

// ---------------- 128x128x128 register-tiled GEMM core ----------------
// A: [128][128] row-major (m,k), B: [128][128] row-major (k,n)
// 256 threads: ty=tid>>4 (8 m-rows each), tx=tid&15 (8 n-cols each = 4 f32x2)
__device__ __forceinline__ void gemm128(const float* __restrict__ A,
                                        const float* __restrict__ B,
                                        u64 acc[8][4], int ty, int tx) {
    const float* Ar0 = A + (ty * 8) * NF;
    const float* Bb  = B + tx * 8;
#pragma unroll 4
    for (int k = 0; k < 128; k++) {
        u64 bv[4];
        const u64* bp = reinterpret_cast<const u64*>(Bb + k * NF);
#pragma unroll
        for (int j = 0; j < 4; j++) bv[j] = bp[j];
#pragma unroll
        for (int i = 0; i < 8; i++) {
            u64 av = pack2(Ar0[i * NF + k]);
#pragma unroll
            for (int j = 0; j < 4; j++) fma2(acc[i][j], av, bv[j]);
        }
    }
}

__device__ __forceinline__ void acc_init_bias(u64 acc[8][4], const float* bias, int tx) {
#pragma unroll
    for (int j = 0; j < 4; j++) {
        u64 bb = *reinterpret_cast<const u64*>(bias + tx * 8 + 2 * j);
#pragma unroll
        for (int i = 0; i < 8; i++) acc[i][j] = bb;
    }
}

// ================= Kernel 1: h = x@W_in + b_in ; zero agg =================
__global__ __launch_bounds__(256, 1)
void k_embed(const float* __restrict__ x, const float* __restrict__ W_in,
             const float* __restrict__ b_in) {
    extern __shared__ float smem[];
    float* s_A = smem;            // 128*128
    float* s_B = smem + 16384;    // 128*128
    float* s_b = smem + 32768;    // 128

    int tid = threadIdx.x;
    int tx = tid & 15, ty = tid >> 4;
    int row0 = blockIdx.x * 128;

    // load W_in
    for (int i = tid; i < 4096; i += 256)
        reinterpret_cast<float4*>(s_B)[i] = reinterpret_cast<const float4*>(W_in)[i];
    // load x tile (guard rows)
    for (int i = tid; i < 4096; i += 256) {
        int r = i >> 5, q = i & 31;
        float4 v = make_float4(0.f, 0.f, 0.f, 0.f);
        if (row0 + r < N_ATOMS) v = reinterpret_cast<const float4*>(x)[(row0 + r) * 32 + q];
        reinterpret_cast<float4*>(s_A)[i] = v;
    }
    if (tid < 128) s_b[tid] = b_in[tid];
    __syncthreads();

    u64 acc[8][4];
    acc_init_bias(acc, s_b, tx);
    gemm128(s_A, s_B, acc, ty, tx);

    float4 z4 = make_float4(0.f, 0.f, 0.f, 0.f);
#pragma unroll
    for (int i = 0; i < 8; i++) {
        int r = row0 + ty * 8 + i;
        if (r < N_ATOMS) {
            float2 p0 = unpack2(acc[i][0]), p1 = unpack2(acc[i][1]);
            float2 p2 = unpack2(acc[i][2]), p3 = unpack2(acc[i][3]);
            float* hp = g_h + r * NF + tx * 8;
            *reinterpret_cast<float4*>(hp)     = make_float4(p0.x, p0.y, p1.x, p1.y);
            *reinterpret_cast<float4*>(hp + 4) = make_float4(p2.x, p2.y, p3.x, p3.y);
            float* ap = g_agg + r * NF + tx * 8;
            *reinterpret_cast<float4*>(ap)     = z4;
            *reinterpret_cast<float4*>(ap + 4) = z4;
        }
    }
}

// ================= Kernel 2: persistent edge kernel =================
// per tile of 128 edges:
//   t   = ssp(f_ij @ Wf1 + bf1)            [128 x 128]
//   Wij = (t @ Wf2 + bf2) * rcut           [128 x 128]
//   agg[idx_i] += h[idx_j] * Wij           (atomicAdd)
__global__ __launch_bounds__(256, 1)
void k_edge(const float* __restrict__ f_ij, const float* __restrict__ rcut,
            const float* __restrict__ Wf1, const float* __restrict__ bf1,
            const float* __restrict__ Wf2, const float* __restrict__ bf2,
            const int* __restrict__ idx_i, const int* __restrict__ idx_j) {
    extern __shared__ float smem[];
    float* s_Wf2  = smem;                 // 16384
    float* s_t    = smem + 16384;         // 16384  [e][k]
    float* s_wij  = smem + 32768;         // 16384  [e][f]
    float* s_f    = smem + 49152;         // 2560   [e][r]
    float* s_Wf1  = smem + 51712;         // 2560   [r][k]
    float* s_bf1  = smem + 54272;         // 128
    float* s_bf2  = smem + 54400;         // 128
    float* s_rc   = smem + 54528;         // 128
    int*   s_ii   = reinterpret_cast<int*>(smem + 54656);  // 128
    int*   s_jj   = reinterpret_cast<int*>(smem + 54784);  // 128

    int tid = threadIdx.x;
    int tx = tid & 15, ty = tid >> 4;

    // one-time weight load
    for (int i = tid; i < 4096; i += 256)
        reinterpret_cast<float4*>(s_Wf2)[i] = reinterpret_cast<const float4*>(Wf2)[i];
    for (int i = tid; i < 640; i += 256)
        reinterpret_cast<float4*>(s_Wf1)[i] = reinterpret_cast<const float4*>(Wf1)[i];
    if (tid < 128) { s_bf1[tid] = bf1[tid]; s_bf2[tid] = bf2[tid]; }
    __syncthreads();

    for (int t = blockIdx.x; t < N_TILES; t += gridDim.x) {
        int e0 = t * E_TILE;
        // ---- Phase A: load edge data ----
        for (int i = tid; i < 640; i += 256)   // 128 edges * 20 rbf / 4
            reinterpret_cast<float4*>(s_f)[i] =
                reinterpret_cast<const float4*>(f_ij)[e0 * 5 + i];
        if (tid < 128) {
            s_rc[tid] = rcut[e0 + tid];
            s_ii[tid] = idx_i[e0 + tid];
            s_jj[tid] = idx_j[e0 + tid];
        }
        __syncthreads();

        // ---- Phase B: t = ssp(f@Wf1 + bf1) ----
        for (int idx = tid; idx < 16384; idx += 256) {
            int e = idx >> 7, k = idx & 127;
            float v = s_bf1[k];
            const float* fe = s_f + e * N_RBF;
#pragma unroll
            for (int r = 0; r < N_RBF; r++) v = fmaf(fe[r], s_Wf1[r * NF + k], v);
            s_t[idx] = sspf(v);
        }
        __syncthreads();

        // ---- Phase C: Wij = (t@Wf2 + bf2) * rcut ----
        {
            u64 acc[8][4];
            acc_init_bias(acc, s_bf2, tx);
            gemm128(s_t, s_Wf2, acc, ty, tx);
#pragma unroll
            for (int i = 0; i < 8; i++) {
                int e = ty * 8 + i;
                float rc = s_rc[e];
                float2 p0 = unpack2(acc[i][0]), p1 = unpack2(acc[i][1]);
                float2 p2 = unpack2(acc[i][2]), p3 = unpack2(acc[i][3]);
                float* wp = s_wij + e * NF + tx * 8;
                *reinterpret_cast<float4*>(wp) =
                    make_float4(p0.x * rc, p0.y * rc, p1.x * rc, p1.y * rc);
                *reinterpret_cast<float4*>(wp + 4) =
                    make_float4(p2.x * rc, p2.y * rc, p3.x * rc, p3.y * rc);
            }
        }
        __syncthreads();

        // ---- Phase D: gather h[idx_j], multiply, scatter-add agg[idx_i] ----
#pragma unroll 4
        for (int idx = tid; idx < 4096; idx += 256) {   // 128 edges * 32 float4
            int e = idx >> 5, q = idx & 31;
            float4 hv = __ldg(reinterpret_cast<const float4*>(g_h) + s_jj[e] * 32 + q);
            float4 wv = reinterpret_cast<const float4*>(s_wij)[idx];
            float* ap = g_agg + s_ii[e] * NF + q * 4;
            atomicAdd(ap + 0, hv.x * wv.x);
            atomicAdd(ap + 1, hv.y * wv.y);
            atomicAdd(ap + 2, hv.z * wv.z);
            atomicAdd(ap + 3, hv.w * wv.w);
        }
        __syncthreads();
    }
}

// ================= Kernel 3: out = ssp(agg@Wo1+bo1)@Wo2 + bo2 =================
__global__ __launch_bounds__(256, 1)
void k_out(const float* __restrict__ Wo1, const float* __restrict__ bo1,
           const float* __restrict__ Wo2, const float* __restrict__ bo2,
           float* __restrict__ out) {
    extern __shared__ float smem[];
    float* s_A  = smem;            // 128*128
    float* s_B  = smem + 16384;    // 128*128
    float* s_b1 = smem + 32768;    // 128
    float* s_b2 = smem + 32896;    // 128

    int tid = threadIdx.x;
    int tx = tid & 15, ty = tid >> 4;
    int row0 = blockIdx.x * 128;

    for (int i = tid; i < 4096; i += 256)
        reinterpret_cast<float4*>(s_B)[i] = reinterpret_cast<const float4*>(Wo1)[i];
    for (int i = tid; i < 4096; i += 256) {
        int r = i >> 5, q = i & 31;
        float4 v = make_float4(0.f, 0.f, 0.f, 0.f);
        if (row0 + r < N_ATOMS) v = reinterpret_cast<const float4*>(g_agg)[(row0 + r) * 32 + q];
        reinterpret_cast<float4*>(s_A)[i] = v;
    }
    if (tid < 128) { s_b1[tid] = bo1[tid]; s_b2[tid] = bo2[tid]; }
    __syncthreads();

    u64 acc[8][4];
    acc_init_bias(acc, s_b1, tx);
    gemm128(s_A, s_B, acc, ty, tx);
    __syncthreads();   // all reads of s_A / s_B done

    // u = ssp(.) into s_A ; load Wo2 into s_B
#pragma unroll
    for (int i = 0; i < 8; i++) {
        float* up = s_A + (ty * 8 + i) * NF + tx * 8;
        float2 p0 = unpack2(acc[i][0]), p1 = unpack2(acc[i][1]);
        float2 p2 = unpack2(acc[i][2]), p3 = unpack2(acc[i][3]);
        up[0] = sspf(p0.x); up[1] = sspf(p0.y);
        up[2] = sspf(p1.x); up[3] = sspf(p1.y);
        up[4] = sspf(p2.x); up[5] = sspf(p2.y);
        up[6] = sspf(p3.x); up[7] = sspf(p3.y);
    }
    for (int i = tid; i < 4096; i += 256)
        reinterpret_cast<float4*>(s_B)[i] = reinterpret_cast<const float4*>(Wo2)[i];
    __syncthreads();

    u64 acc2[8][4];
    acc_init_bias(acc2, s_b2, tx);
    gemm128(s_A, s_B, acc2, ty, tx);

#pragma unroll
    for (int i = 0; i < 8; i++) {
        int r = row0 + ty * 8 + i;
        if (r < N_ATOMS) {
            float2 p0 = unpack2(acc2[i][0]), p1 = unpack2(acc2[i][1]);
            float2 p2 = unpack2(acc2[i][2]), p3 = unpack2(acc2[i][3]);
            float* op = out + r * NF + tx * 8;
            *reinterpret_cast<float4*>(op)     = make_float4(p0.x, p0.y, p1.x, p1.y);
            *reinterpret_cast<float4*>(op + 4) = make_float4(p2.x, p2.y, p3.x, p3.y);
        }
    }
}

// ================= launch =================
extern "C" void kernel_launch(void* const* d_in, const int* in_sizes, int n_in,
                              void* d_out, int out_size) {
    const float* x     = (const float*)d_in[0];
    const float* f_ij  = (const float*)d_in[1];
    const float* rcut  = (const float*)d_in[2];
    const float* W_in  = (const float*)d_in[3];
    const float* b_in  = (const float*)d_in[4];
    const float* Wf1   = (const float*)d_in[5];
    const float* bf1   = (const float*)d_in[6];
    const float* Wf2   = (const float*)d_in[7];
    const float* bf2   = (const float*)d_in[8];
    const float* Wo1   = (const float*)d_in[9];
    const float* bo1   = (const float*)d_in[10];
    const float* Wo2   = (const float*)d_in[11];
    const float* bo2   = (const float*)d_in[12];
    const int*   idx_i = (const int*)d_in[13];
    const int*   idx_j = (const int*)d_in[14];
    float* out = (float*)d_out;

    size_t smem_embed = (2 * 16384 + 128) * sizeof(float);
    size_t smem_edge  = (3 * 16384 + 2 * 2560 + 4 * 128 + 2 * 128) * sizeof(float);
    size_t smem_out   = (2 * 16384 + 256) * sizeof(float);

    cudaFuncSetAttribute(k_embed, cudaFuncAttributeMaxDynamicSharedMemorySize, (int)smem_embed);
    cudaFuncSetAttribute(k_edge,  cudaFuncAttributeMaxDynamicSharedMemorySize, (int)smem_edge);
    cudaFuncSetAttribute(k_out,   cudaFuncAttributeMaxDynamicSharedMemorySize, (int)smem_out);

    int nsm = 148;
    cudaDeviceGetAttribute(&nsm, cudaDevAttrMultiProcessorCount, 0);

    int node_blocks = (N_ATOMS + 127) / 128;   // 391

    k_embed<<<node_blocks, 256, smem_embed>>>(x, W_in, b_in);
    k_edge<<<nsm, 256, smem_edge>>>(f_ij, rcut, Wf1, bf1, Wf2, bf2, idx_i, idx_j);
    k_out<<<node_blocks, 256, smem_out>>>(Wo1, bo1, Wo2, bo2, out);
}

// round 4
// speedup vs baseline: 1.6261x; 1.6261x over previous
#include <cuda_runtime.h>
#include <cuda_bf16.h>
#include <cstdint>

// Problem constants
#define N_ATOMS   50000
#define N_PAIRS   1600000
#define NF        128
#define N_RBF     20
#define E_TILE    128
#define N_TILES   (N_PAIRS / E_TILE)   // 12500
#define LOG2F_C   0.69314718055994530942f

typedef unsigned long long u64;

// ---------------- scratch ----------------
__device__ float g_h[N_ATOMS * NF];
__device__ float g_agg[N_ATOMS * NF];

// ---------------- small helpers ----------------
__device__ __forceinline__ uint32_t smem_u32(const void* p) {
    uint32_t a;
    asm("{ .reg .u64 t; cvta.to.shared.u64 t, %1; cvt.u32.u64 %0, t; }" : "=r"(a) : "l"(p));
    return a;
}
__device__ __forceinline__ u64 pack2(float x) {
    u64 d; unsigned v = __float_as_uint(x);
    asm("mov.b64 %0, {%1, %1};" : "=l"(d) : "r"(v));
    return d;
}
__device__ __forceinline__ void fma2(u64& d, u64 a, u64 b) {
    asm("fma.rn.f32x2 %0, %1, %2, %0;" : "+l"(d) : "l"(a), "l"(b));
}
__device__ __forceinline__ float2 unpack2(u64 d) {
    unsigned lo, hi;
    asm("mov.b64 {%0, %1}, %2;" : "=r"(lo), "=r"(hi) : "l"(d));
    return make_float2(__uint_as_float(lo), __uint_as_float(hi));
}
__device__ __forceinline__ float sspf(float x) {
    float e = __expf(-fabsf(x));
    return fmaxf(x, 0.0f) + __logf(1.0f + e) - LOG2F_C;
}
__device__ __forceinline__ void red4(float* p, float a, float b, float c, float d) {
    asm volatile("red.global.add.v4.f32 [%0], {%1,%2,%3,%4};"
                 :: "l"(p), "f"(a), "f"(b), "f"(c), "f"(d) : "memory");
}

// ---------------- warp-MMA primitives (plain sm_80+ PTX, compiles for compute_103) ----------------
__device__ __forceinline__ void ldmx4(uint32_t r[4], uint32_t addr) {
    asm volatile("ldmatrix.sync.aligned.m8n8.x4.shared.b16 {%0,%1,%2,%3}, [%4];"
                 : "=r"(r[0]), "=r"(r[1]), "=r"(r[2]), "=r"(r[3]) : "r"(addr));
}
__device__ __forceinline__ void mma16816(float d[4], const uint32_t a[4],
                                         uint32_t b0, uint32_t b1) {
    asm volatile(
        "mma.sync.aligned.m16n8k16.row.col.f32.bf16.bf16.f32 "
        "{%0,%1,%2,%3}, {%4,%5,%6,%7}, {%8,%9}, {%0,%1,%2,%3};"
        : "+f"(d[0]), "+f"(d[1]), "+f"(d[2]), "+f"(d[3])
        : "r"(a[0]), "r"(a[1]), "r"(a[2]), "r"(a[3]), "r"(b0), "r"(b1));
}

// ---------------- f32x2 register-tiled GEMM (node kernels) ----------------
__device__ __forceinline__ void gemm128(const float* __restrict__ A,
                                        const float* __restrict__ B,
                                        u64 acc[8][4], int ty, int tx) {
    const float* Ar0 = A + (ty * 8) * NF;
    const float* Bb  = B + tx * 8;
#pragma unroll 4
    for (int k = 0; k < 128; k++) {
        u64 bv[4];
        const u64* bp = reinterpret_cast<const u64*>(Bb + k * NF);
#pragma unroll
        for (int j = 0; j < 4; j++) bv[j] = bp[j];
#pragma unroll
        for (int i = 0; i < 8; i++) {
            u64 av = pack2(Ar0[i * NF + k]);
#pragma unroll
            for (int j = 0; j < 4; j++) fma2(acc[i][j], av, bv[j]);
        }
    }
}
__device__ __forceinline__ void acc_init_bias(u64 acc[8][4], const float* bias, int tx) {
#pragma unroll
    for (int j = 0; j < 4; j++) {
        u64 bb = *reinterpret_cast<const u64*>(bias + tx * 8 + 2 * j);
#pragma unroll
        for (int i = 0; i < 8; i++) acc[i][j] = bb;
    }
}

// ================= Kernel 1: h = x@W_in + b_in ; zero agg =================
__global__ __launch_bounds__(256, 1)
void k_embed(const float* __restrict__ x, const float* __restrict__ W_in,
             const float* __restrict__ b_in) {
    extern __shared__ float smem[];
    float* s_A = smem;
    float* s_B = smem + 16384;
    float* s_b = smem + 32768;

    int tid = threadIdx.x;
    int tx = tid & 15, ty = tid >> 4;
    int row0 = blockIdx.x * 128;

    for (int i = tid; i < 4096; i += 256)
        reinterpret_cast<float4*>(s_B)[i] = reinterpret_cast<const float4*>(W_in)[i];
    for (int i = tid; i < 4096; i += 256) {
        int r = i >> 5, q = i & 31;
        float4 v = make_float4(0.f, 0.f, 0.f, 0.f);
        if (row0 + r < N_ATOMS) v = reinterpret_cast<const float4*>(x)[(row0 + r) * 32 + q];
        reinterpret_cast<float4*>(s_A)[i] = v;
    }
    if (tid < 128) s_b[tid] = b_in[tid];
    __syncthreads();

    u64 acc[8][4];
    acc_init_bias(acc, s_b, tx);
    gemm128(s_A, s_B, acc, ty, tx);

    float4 z4 = make_float4(0.f, 0.f, 0.f, 0.f);
#pragma unroll
    for (int i = 0; i < 8; i++) {
        int r = row0 + ty * 8 + i;
        if (r < N_ATOMS) {
            float2 p0 = unpack2(acc[i][0]), p1 = unpack2(acc[i][1]);
            float2 p2 = unpack2(acc[i][2]), p3 = unpack2(acc[i][3]);
            float* hp = g_h + r * NF + tx * 8;
            *reinterpret_cast<float4*>(hp)     = make_float4(p0.x, p0.y, p1.x, p1.y);
            *reinterpret_cast<float4*>(hp + 4) = make_float4(p2.x, p2.y, p3.x, p3.y);
            float* ap = g_agg + r * NF + tx * 8;
            *reinterpret_cast<float4*>(ap)     = z4;
            *reinterpret_cast<float4*>(ap + 4) = z4;
        }
    }
}

// ================= Kernel 2: persistent edge kernel (warp HMMA) =================
// A tiles (t hi/lo, [128e x 128k] bf16, stride 136) aliased with s_wij.
#define ASTRIDE   136                         // bf16 elems; 272 B row stride
#define ATILE_B   (128 * ASTRIDE * 2)         // 34816 B
#define OFF_AHI   0
#define OFF_ALO   ATILE_B                     // 34816
#define OFF_WIJ   0                           // aliases A (128*132*4 = 67584 <= 69632)
#define OFF_BHI   (2 * ATILE_B)               // 69632
#define OFF_BLO   (OFF_BHI + ATILE_B)         // 104448
#define OFF_F     (OFF_BLO + ATILE_B)         // 139264 (2560 f32)
#define OFF_WF1   (OFF_F + 2560 * 4)          // 149504 (2560 f32)
#define OFF_BF1   (OFF_WF1 + 2560 * 4)        // 159744
#define OFF_BF2   (OFF_BF1 + 512)
#define OFF_RC    (OFF_BF2 + 512)
#define OFF_II    (OFF_RC + 512)
#define OFF_JJ    (OFF_II + 512)
#define EDGE_SMEM (OFF_JJ + 512)              // 162304

__global__ __launch_bounds__(256, 1)
void k_edge(const float* __restrict__ f_ij, const float* __restrict__ rcut,
            const float* __restrict__ Wf1, const float* __restrict__ bf1,
            const float* __restrict__ Wf2, const float* __restrict__ bf2,
            const int* __restrict__ idx_i, const int* __restrict__ idx_j) {
    extern __shared__ __align__(1024) char sm[];
    char*  s_Ahi = sm + OFF_AHI;
    char*  s_Alo = sm + OFF_ALO;
    char*  s_Bhi = sm + OFF_BHI;
    char*  s_Blo = sm + OFF_BLO;
    float* s_wij = reinterpret_cast<float*>(sm + OFF_WIJ);   // stride 132 f32
    float* s_f   = reinterpret_cast<float*>(sm + OFF_F);
    float* s_Wf1 = reinterpret_cast<float*>(sm + OFF_WF1);
    float* s_bf1 = reinterpret_cast<float*>(sm + OFF_BF1);
    float* s_bf2 = reinterpret_cast<float*>(sm + OFF_BF2);
    float* s_rc  = reinterpret_cast<float*>(sm + OFF_RC);
    int*   s_ii  = reinterpret_cast<int*>(sm + OFF_II);
    int*   s_jj  = reinterpret_cast<int*>(sm + OFF_JJ);

    int tid  = threadIdx.x;
    int wid  = tid >> 5, lane = tid & 31;
    uint32_t sbase = smem_u32(sm);

    // one-time weights: Bt[n][k] = Wf2[k][n], split hi/lo bf16
    for (int i = tid; i < 16384; i += 256) {
        int n = i >> 7, k = i & 127;
        float w = Wf2[k * NF + n];
        __nv_bfloat16 h = __float2bfloat16(w);
        float lo = w - __bfloat162float(h);
        uint32_t o = (uint32_t)(n * ASTRIDE + k) * 2u;
        *reinterpret_cast<__nv_bfloat16*>(s_Bhi + o) = h;
        *reinterpret_cast<__nv_bfloat16*>(s_Blo + o) = __float2bfloat16(lo);
    }
    for (int i = tid; i < 2560; i += 256) s_Wf1[i] = Wf1[i];
    if (tid < 128) { s_bf1[tid] = bf1[tid]; s_bf2[tid] = bf2[tid]; }

    // per-warp MMA geometry
    int m0 = wid * 16;                 // 16 output rows per warp
    int lr = lane & 15;                // ldmatrix row lane
    int lc = (lane >> 4) * 8;          // ldmatrix col half
    uint32_t aAhi = sbase + OFF_AHI;
    uint32_t aAlo = sbase + OFF_ALO;
    uint32_t aBhi = sbase + OFF_BHI;
    uint32_t aBlo = sbase + OFF_BLO;
    int g  = lane >> 2;                // acc row within m16
    int tg = lane & 3;                 // acc col pair

    for (int t = blockIdx.x; t < N_TILES; t += gridDim.x) {
        __syncthreads();   // prev tile phase D done
        int e0 = t * E_TILE;

        // ---- Phase A: edge data ----
        for (int i = tid; i < 640; i += 256)
            reinterpret_cast<float4*>(s_f)[i] = reinterpret_cast<const float4*>(f_ij)[e0 * 5 + i];
        if (tid < 128) {
            s_rc[tid] = rcut[e0 + tid];
            s_ii[tid] = idx_i[e0 + tid];
            s_jj[tid] = idx_j[e0 + tid];
        }
        __syncthreads();

        // ---- Phase B: t = ssp(f@Wf1+bf1) -> bf16 hi/lo into A tiles ----
        for (int idx = tid; idx < 8192; idx += 256) {
            int e = idx >> 6;
            int c = (idx & 63) * 2;
            u64 v2 = *reinterpret_cast<const u64*>(s_bf1 + c);
            const float* fe = s_f + e * N_RBF;
#pragma unroll
            for (int r = 0; r < N_RBF; r++)
                fma2(v2, pack2(fe[r]), *reinterpret_cast<const u64*>(s_Wf1 + r * NF + c));
            float2 xv = unpack2(v2);
            float x0 = sspf(xv.x), x1 = sspf(xv.y);
            uint32_t uh;
            asm("cvt.rn.bf16x2.f32 %0, %1, %2;" : "=r"(uh) : "f"(x1), "f"(x0));
            float h0 = __uint_as_float(uh << 16);
            float h1 = __uint_as_float(uh & 0xFFFF0000u);
            float l0 = x0 - h0, l1 = x1 - h1;
            uint32_t ul;
            asm("cvt.rn.bf16x2.f32 %0, %1, %2;" : "=r"(ul) : "f"(l1), "f"(l0));
            uint32_t o = (uint32_t)(e * ASTRIDE + c) * 2u;
            *reinterpret_cast<uint32_t*>(s_Ahi + o) = uh;
            *reinterpret_cast<uint32_t*>(s_Alo + o) = ul;
        }
        __syncthreads();

        // ---- Phase C: Wij = Ah@Bh + Al@Bh + Ah@Bl (HMMA) ----
        // preload A fragments for all 8 k-steps (reused across the 128 N cols)
        uint32_t ah[8][4], al[8][4];
        {
            uint32_t rowb = (uint32_t)((m0 + lr) * ASTRIDE) * 2u;
#pragma unroll
            for (int k = 0; k < 8; k++) {
                uint32_t cb = (uint32_t)(k * 16 + lc) * 2u;
                ldmx4(ah[k], aAhi + rowb + cb);
                ldmx4(al[k], aAlo + rowb + cb);
            }
        }

        float acc[8][2][4];
#pragma unroll
        for (int np = 0; np < 8; np++) {
#pragma unroll
            for (int h = 0; h < 2; h++)
#pragma unroll
                for (int j = 0; j < 4; j++) acc[np][h][j] = 0.f;
            uint32_t nrow = (uint32_t)((np * 16 + lr) * ASTRIDE) * 2u;
#pragma unroll
            for (int k = 0; k < 8; k++) {
                uint32_t cb = (uint32_t)(k * 16 + lc) * 2u;
                uint32_t bh[4], bl[4];
                ldmx4(bh, aBhi + nrow + cb);
                ldmx4(bl, aBlo + nrow + cb);
                mma16816(acc[np][0], ah[k], bh[0], bh[2]);
                mma16816(acc[np][0], al[k], bh[0], bh[2]);
                mma16816(acc[np][0], ah[k], bl[0], bl[2]);
                mma16816(acc[np][1], ah[k], bh[1], bh[3]);
                mma16816(acc[np][1], al[k], bh[1], bh[3]);
                mma16816(acc[np][1], ah[k], bl[1], bl[3]);
            }
        }
        __syncthreads();   // all A/B smem reads done before wij overwrites A

        // epilogue: bias + rcut, stage rows into s_wij (stride 132)
        {
            int r0 = m0 + g, r1 = m0 + g + 8;
            float rc0 = s_rc[r0], rc1 = s_rc[r1];
            float* w0 = s_wij + r0 * 132;
            float* w1 = s_wij + r1 * 132;
#pragma unroll
            for (int np = 0; np < 8; np++) {
                int c0 = np * 16 + 2 * tg;
                int c1 = c0 + 8;
                float b00 = s_bf2[c0], b01 = s_bf2[c0 + 1];
                float b10 = s_bf2[c1], b11 = s_bf2[c1 + 1];
                *reinterpret_cast<float2*>(w0 + c0) =
                    make_float2((acc[np][0][0] + b00) * rc0, (acc[np][0][1] + b01) * rc0);
                *reinterpret_cast<float2*>(w0 + c1) =
                    make_float2((acc[np][1][0] + b10) * rc0, (acc[np][1][1] + b11) * rc0);
                *reinterpret_cast<float2*>(w1 + c0) =
                    make_float2((acc[np][0][2] + b00) * rc1, (acc[np][0][3] + b01) * rc1);
                *reinterpret_cast<float2*>(w1 + c1) =
                    make_float2((acc[np][1][2] + b10) * rc1, (acc[np][1][3] + b11) * rc1);
            }
        }
        __syncthreads();

        // ---- Phase D: gather h[idx_j] * wij, vector-red into agg[idx_i] ----
#pragma unroll 4
        for (int idx = tid; idx < 4096; idx += 256) {
            int e = idx >> 5, q = idx & 31;
            float4 hv = __ldg(reinterpret_cast<const float4*>(g_h) + s_jj[e] * 32 + q);
            float4 wv = *reinterpret_cast<const float4*>(s_wij + e * 132 + q * 4);
            float* ap = g_agg + s_ii[e] * NF + q * 4;
            red4(ap, hv.x * wv.x, hv.y * wv.y, hv.z * wv.z, hv.w * wv.w);
        }
    }
}

// ================= Kernel 3: out = ssp(agg@Wo1+bo1)@Wo2 + bo2 =================
__global__ __launch_bounds__(256, 1)
void k_out(const float* __restrict__ Wo1, const float* __restrict__ bo1,
           const float* __restrict__ Wo2, const float* __restrict__ bo2,
           float* __restrict__ out) {
    extern __shared__ float smem[];
    float* s_A  = smem;
    float* s_B  = smem + 16384;
    float* s_b1 = smem + 32768;
    float* s_b2 = smem + 32896;

    int tid = threadIdx.x;
    int tx = tid & 15, ty = tid >> 4;
    int row0 = blockIdx.x * 128;

    for (int i = tid; i < 4096; i += 256)
        reinterpret_cast<float4*>(s_B)[i] = reinterpret_cast<const float4*>(Wo1)[i];
    for (int i = tid; i < 4096; i += 256) {
        int r = i >> 5, q = i & 31;
        float4 v = make_float4(0.f, 0.f, 0.f, 0.f);
        if (row0 + r < N_ATOMS) v = reinterpret_cast<const float4*>(g_agg)[(row0 + r) * 32 + q];
        reinterpret_cast<float4*>(s_A)[i] = v;
    }
    if (tid < 128) { s_b1[tid] = bo1[tid]; s_b2[tid] = bo2[tid]; }
    __syncthreads();

    u64 acc[8][4];
    acc_init_bias(acc, s_b1, tx);
    gemm128(s_A, s_B, acc, ty, tx);
    __syncthreads();

#pragma unroll
    for (int i = 0; i < 8; i++) {
        float* up = s_A + (ty * 8 + i) * NF + tx * 8;
        float2 p0 = unpack2(acc[i][0]), p1 = unpack2(acc[i][1]);
        float2 p2 = unpack2(acc[i][2]), p3 = unpack2(acc[i][3]);
        up[0] = sspf(p0.x); up[1] = sspf(p0.y);
        up[2] = sspf(p1.x); up[3] = sspf(p1.y);
        up[4] = sspf(p2.x); up[5] = sspf(p2.y);
        up[6] = sspf(p3.x); up[7] = sspf(p3.y);
    }
    for (int i = tid; i < 4096; i += 256)
        reinterpret_cast<float4*>(s_B)[i] = reinterpret_cast<const float4*>(Wo2)[i];
    __syncthreads();

    u64 acc2[8][4];
    acc_init_bias(acc2, s_b2, tx);
    gemm128(s_A, s_B, acc2, ty, tx);

#pragma unroll
    for (int i = 0; i < 8; i++) {
        int r = row0 + ty * 8 + i;
        if (r < N_ATOMS) {
            float2 p0 = unpack2(acc2[i][0]), p1 = unpack2(acc2[i][1]);
            float2 p2 = unpack2(acc2[i][2]), p3 = unpack2(acc2[i][3]);
            float* op = out + r * NF + tx * 8;
            *reinterpret_cast<float4*>(op)     = make_float4(p0.x, p0.y, p1.x, p1.y);
            *reinterpret_cast<float4*>(op + 4) = make_float4(p2.x, p2.y, p3.x, p3.y);
        }
    }
}

// ================= launch =================
extern "C" void kernel_launch(void* const* d_in, const int* in_sizes, int n_in,
                              void* d_out, int out_size) {
    const float* x     = (const float*)d_in[0];
    const float* f_ij  = (const float*)d_in[1];
    const float* rcut  = (const float*)d_in[2];
    const float* W_in  = (const float*)d_in[3];
    const float* b_in  = (const float*)d_in[4];
    const float* Wf1   = (const float*)d_in[5];
    const float* bf1   = (const float*)d_in[6];
    const float* Wf2   = (const float*)d_in[7];
    const float* bf2   = (const float*)d_in[8];
    const float* Wo1   = (const float*)d_in[9];
    const float* bo1   = (const float*)d_in[10];
    const float* Wo2   = (const float*)d_in[11];
    const float* bo2   = (const float*)d_in[12];
    const int*   idx_i = (const int*)d_in[13];
    const int*   idx_j = (const int*)d_in[14];
    float* out = (float*)d_out;

    size_t smem_embed = (2 * 16384 + 128) * sizeof(float);
    size_t smem_edge  = EDGE_SMEM;
    size_t smem_out   = (2 * 16384 + 256) * sizeof(float);

    cudaFuncSetAttribute(k_embed, cudaFuncAttributeMaxDynamicSharedMemorySize, (int)smem_embed);
    cudaFuncSetAttribute(k_edge,  cudaFuncAttributeMaxDynamicSharedMemorySize, (int)smem_edge);
    cudaFuncSetAttribute(k_out,   cudaFuncAttributeMaxDynamicSharedMemorySize, (int)smem_out);

    int nsm = 148;
    cudaDeviceGetAttribute(&nsm, cudaDevAttrMultiProcessorCount, 0);

    int node_blocks = (N_ATOMS + 127) / 128;   // 391

    k_embed<<<node_blocks, 256, smem_embed>>>(x, W_in, b_in);
    k_edge<<<nsm, 256, smem_edge>>>(f_ij, rcut, Wf1, bf1, Wf2, bf2, idx_i, idx_j);
    k_out<<<node_blocks, 256, smem_out>>>(Wo1, bo1, Wo2, bo2, out);
}

// round 7
// speedup vs baseline: 2.5239x; 1.5522x over previous
#include <cuda_runtime.h>
#include <cuda_bf16.h>
#include <cstdint>

#define N_ATOMS   50000
#define N_PAIRS   1600000
#define NF        128
#define N_RBF     20
#define E_TILE    128
#define N_TILES   (N_PAIRS / E_TILE)   // 12500
#define LOG2F_C   0.69314718055994530942f

typedef unsigned long long u64;

// ---------------- scratch ----------------
__device__ float g_h[N_ATOMS * NF];
__device__ float g_agg[N_ATOMS * NF];

// ---------------- helpers ----------------
__device__ __forceinline__ uint32_t smem_u32(const void* p) {
    uint32_t a;
    asm("{ .reg .u64 t; cvta.to.shared.u64 t, %1; cvt.u32.u64 %0, t; }" : "=r"(a) : "l"(p));
    return a;
}
__device__ __forceinline__ float sspf(float x) {
    float e = __expf(-fabsf(x));
    return fmaxf(x, 0.0f) + __logf(1.0f + e) - LOG2F_C;
}
__device__ __forceinline__ void red4(float* p, float a, float b, float c, float d) {
    asm volatile("red.global.add.v4.f32 [%0], {%1,%2,%3,%4};"
                 :: "l"(p), "f"(a), "f"(b), "f"(c), "f"(d) : "memory");
}
__device__ __forceinline__ float to_tf32(float x) {
    uint32_t u; asm("cvt.rna.tf32.f32 %0, %1;" : "=r"(u) : "f"(x));
    return __uint_as_float(u);
}
// pack (x0 -> low, x1 -> high) bf16x2
__device__ __forceinline__ uint32_t pack_bf16(float x0, float x1) {
    uint32_t u; asm("cvt.rn.bf16x2.f32 %0, %1, %2;" : "=r"(u) : "f"(x1), "f"(x0));
    return u;
}

// ---------------- MMA primitives ----------------
__device__ __forceinline__ void ldmx4(uint32_t r[4], uint32_t addr) {
    asm volatile("ldmatrix.sync.aligned.m8n8.x4.shared.b16 {%0,%1,%2,%3}, [%4];"
                 : "=r"(r[0]), "=r"(r[1]), "=r"(r[2]), "=r"(r[3]) : "r"(addr));
}
__device__ __forceinline__ void mma16816(float d[4], const uint32_t a[4],
                                         uint32_t b0, uint32_t b1) {
    asm volatile(
        "mma.sync.aligned.m16n8k16.row.col.f32.bf16.bf16.f32 "
        "{%0,%1,%2,%3}, {%4,%5,%6,%7}, {%8,%9}, {%0,%1,%2,%3};"
        : "+f"(d[0]), "+f"(d[1]), "+f"(d[2]), "+f"(d[3])
        : "r"(a[0]), "r"(a[1]), "r"(a[2]), "r"(a[3]), "r"(b0), "r"(b1));
}
__device__ __forceinline__ void mma_tf32(float d[4], const uint32_t a[4],
                                         uint32_t b0, uint32_t b1) {
    asm volatile(
        "mma.sync.aligned.m16n8k8.row.col.f32.tf32.tf32.f32 "
        "{%0,%1,%2,%3}, {%4,%5,%6,%7}, {%8,%9}, {%0,%1,%2,%3};"
        : "+f"(d[0]), "+f"(d[1]), "+f"(d[2]), "+f"(d[3])
        : "r"(a[0]), "r"(a[1]), "r"(a[2]), "r"(a[3]), "r"(b0), "r"(b1));
}

// ---------------- shared 3-pass bf16 HMMA core ----------------
// A tile: [128 m][136 k] bf16 hi/lo, B tile: [128 n][136 k] bf16 hi/lo (both 272B row stride)
// Per warp: rows m0..m0+15, all 128 cols. acc[np][half][4].
__device__ __forceinline__ void hmma3(uint32_t aAhi, uint32_t aAlo,
                                      uint32_t aBhi, uint32_t aBlo,
                                      int m0, int lane, float acc[8][2][4]) {
    int lr = lane & 15;
    int lc = (lane >> 4) * 8;
    uint32_t ah[8][4], al[8][4];
    uint32_t rowb = (uint32_t)((m0 + lr) * 272);
#pragma unroll
    for (int k = 0; k < 8; k++) {
        uint32_t cb = (uint32_t)(k * 16 + lc) * 2u;
        ldmx4(ah[k], aAhi + rowb + cb);
        ldmx4(al[k], aAlo + rowb + cb);
    }
#pragma unroll
    for (int np = 0; np < 8; np++) {
#pragma unroll
        for (int h = 0; h < 2; h++)
#pragma unroll
            for (int j = 0; j < 4; j++) acc[np][h][j] = 0.f;
        uint32_t nrow = (uint32_t)((np * 16 + lr) * 272);
#pragma unroll
        for (int k = 0; k < 8; k++) {
            uint32_t cb = (uint32_t)(k * 16 + lc) * 2u;
            uint32_t bh[4], bl[4];
            ldmx4(bh, aBhi + nrow + cb);
            ldmx4(bl, aBlo + nrow + cb);
            mma16816(acc[np][0], ah[k], bh[0], bh[2]);
            mma16816(acc[np][0], al[k], bh[0], bh[2]);
            mma16816(acc[np][0], ah[k], bl[0], bl[2]);
            mma16816(acc[np][1], ah[k], bh[1], bh[3]);
            mma16816(acc[np][1], al[k], bh[1], bh[3]);
            mma16816(acc[np][1], ah[k], bl[1], bl[3]);
        }
    }
}

// split fp32 -> bf16 hi/lo, store u32 pairs
__device__ __forceinline__ void split_store(char* hi, char* lo, uint32_t off,
                                            float x0, float x1) {
    uint32_t uh = pack_bf16(x0, x1);
    float h0 = __uint_as_float(uh << 16);
    float h1 = __uint_as_float(uh & 0xFFFF0000u);
    uint32_t ul = pack_bf16(x0 - h0, x1 - h1);
    *reinterpret_cast<uint32_t*>(hi + off) = uh;
    *reinterpret_cast<uint32_t*>(lo + off) = ul;
}

// ================= Kernel 1: h = x@W_in + b_in ; zero agg =================
#define EMB_AHI 0
#define EMB_ALO 34816
#define EMB_BHI 69632
#define EMB_BLO 104448
#define EMB_B   139264
#define EMB_SMEM (EMB_B + 512)

__global__ __launch_bounds__(256, 1)
void k_embed(const float* __restrict__ x, const float* __restrict__ W_in,
             const float* __restrict__ b_in) {
    extern __shared__ __align__(1024) char sm[];
    float* s_b = reinterpret_cast<float*>(sm + EMB_B);
    int tid = threadIdx.x, wid = tid >> 5, lane = tid & 31;
    int m0 = wid * 16;
    int row0 = blockIdx.x * 128;
    uint32_t sbase = smem_u32(sm);

    // W_in^T split -> B tiles
    for (int i = tid; i < 16384; i += 256) {
        int n = i >> 7, k = i & 127;
        float w = W_in[k * NF + n];
        __nv_bfloat16 h = __float2bfloat16(w);
        uint32_t o = (uint32_t)(n * 136 + k) * 2u;
        *reinterpret_cast<__nv_bfloat16*>(sm + EMB_BHI + o) = h;
        *reinterpret_cast<__nv_bfloat16*>(sm + EMB_BLO + o) = __float2bfloat16(w - __bfloat162float(h));
    }
    // x tile split -> A tiles
    for (int i = tid; i < 16384; i += 256) {
        int r = i >> 7, c = i & 127;
        float v = (row0 + r < N_ATOMS) ? x[(size_t)(row0 + r) * NF + c] : 0.f;
        __nv_bfloat16 h = __float2bfloat16(v);
        uint32_t o = (uint32_t)(r * 136 + c) * 2u;
        *reinterpret_cast<__nv_bfloat16*>(sm + EMB_AHI + o) = h;
        *reinterpret_cast<__nv_bfloat16*>(sm + EMB_ALO + o) = __float2bfloat16(v - __bfloat162float(h));
    }
    if (tid < 128) s_b[tid] = b_in[tid];
    __syncthreads();

    float acc[8][2][4];
    hmma3(sbase + EMB_AHI, sbase + EMB_ALO, sbase + EMB_BHI, sbase + EMB_BLO,
          m0, lane, acc);

    int g = lane >> 2, tg = lane & 3;
    int r0 = row0 + m0 + g, r1 = r0 + 8;
    float2 z2 = make_float2(0.f, 0.f);
#pragma unroll
    for (int np = 0; np < 8; np++) {
        int c0 = np * 16 + 2 * tg, c1 = c0 + 8;
        if (r0 < N_ATOMS) {
            *reinterpret_cast<float2*>(g_h + (size_t)r0 * NF + c0) =
                make_float2(acc[np][0][0] + s_b[c0], acc[np][0][1] + s_b[c0 + 1]);
            *reinterpret_cast<float2*>(g_h + (size_t)r0 * NF + c1) =
                make_float2(acc[np][1][0] + s_b[c1], acc[np][1][1] + s_b[c1 + 1]);
            *reinterpret_cast<float2*>(g_agg + (size_t)r0 * NF + c0) = z2;
            *reinterpret_cast<float2*>(g_agg + (size_t)r0 * NF + c1) = z2;
        }
        if (r1 < N_ATOMS) {
            *reinterpret_cast<float2*>(g_h + (size_t)r1 * NF + c0) =
                make_float2(acc[np][0][2] + s_b[c0], acc[np][0][3] + s_b[c0 + 1]);
            *reinterpret_cast<float2*>(g_h + (size_t)r1 * NF + c1) =
                make_float2(acc[np][1][2] + s_b[c1], acc[np][1][3] + s_b[c1 + 1]);
            *reinterpret_cast<float2*>(g_agg + (size_t)r1 * NF + c0) = z2;
            *reinterpret_cast<float2*>(g_agg + (size_t)r1 * NF + c1) = z2;
        }
    }
}

// ================= Kernel 2: persistent edge kernel =================
#define OFF_AHI   0
#define OFF_ALO   34816
#define OFF_WIJ   0                    // aliases A tiles (67584 <= 69632)
#define OFF_BHI   69632
#define OFF_BLO   104448
#define OFF_F     139264               // [128][28] f32 = 14336
#define OFF_WF1   153600               // [24][136] f32 = 13056
#define OFF_BF1   166656
#define OFF_BF2   167168
#define OFF_RC    167680
#define OFF_II    168192
#define OFF_JJ    168704
#define EDGE_SMEM 169216

__global__ __launch_bounds__(256, 1)
void k_edge(const float* __restrict__ f_ij, const float* __restrict__ rcut,
            const float* __restrict__ Wf1, const float* __restrict__ bf1,
            const float* __restrict__ Wf2, const float* __restrict__ bf2,
            const int* __restrict__ idx_i, const int* __restrict__ idx_j) {
    extern __shared__ __align__(1024) char sm[];
    char*  s_Ahi = sm + OFF_AHI;
    char*  s_Alo = sm + OFF_ALO;
    float* s_wij = reinterpret_cast<float*>(sm + OFF_WIJ);
    float* s_f   = reinterpret_cast<float*>(sm + OFF_F);
    float* s_Wf1 = reinterpret_cast<float*>(sm + OFF_WF1);
    float* s_bf1 = reinterpret_cast<float*>(sm + OFF_BF1);
    float* s_bf2 = reinterpret_cast<float*>(sm + OFF_BF2);
    float* s_rc  = reinterpret_cast<float*>(sm + OFF_RC);
    int*   s_ii  = reinterpret_cast<int*>(sm + OFF_II);
    int*   s_jj  = reinterpret_cast<int*>(sm + OFF_JJ);

    int tid = threadIdx.x, wid = tid >> 5, lane = tid & 31;
    int m0 = wid * 16;
    int g = lane >> 2, tg = lane & 3;
    uint32_t sbase = smem_u32(sm);

    // ---- one-time init ----
    for (int i = tid; i < 3584; i += 256) s_f[i] = 0.f;     // zero incl. k-pad cols
    for (int i = tid; i < 3264; i += 256) s_Wf1[i] = 0.f;
    __syncthreads();
    for (int i = tid; i < 2560; i += 256) {
        int k = i >> 7, n = i & 127;
        s_Wf1[k * 136 + n] = to_tf32(Wf1[i]);
    }
    for (int i = tid; i < 16384; i += 256) {
        int n = i >> 7, k = i & 127;
        float w = Wf2[k * NF + n];
        __nv_bfloat16 h = __float2bfloat16(w);
        uint32_t o = (uint32_t)(n * 136 + k) * 2u;
        *reinterpret_cast<__nv_bfloat16*>(sm + OFF_BHI + o) = h;
        *reinterpret_cast<__nv_bfloat16*>(sm + OFF_BLO + o) = __float2bfloat16(w - __bfloat162float(h));
    }
    if (tid < 128) { s_bf1[tid] = bf1[tid]; s_bf2[tid] = bf2[tid]; }
    __syncthreads();

    for (int t = blockIdx.x; t < N_TILES; t += gridDim.x) {
        __syncthreads();   // prev tile phase D fully done
        int e0 = t * E_TILE;

        // ---- Phase A: edge data (one thread per edge) ----
        if (tid < 128) {
            int e = tid;
            const float4* fp = reinterpret_cast<const float4*>(f_ij + (size_t)(e0 + e) * 20);
            float fe[20];
#pragma unroll
            for (int i = 0; i < 5; i++) {
                float4 v = fp[i];
                fe[i * 4 + 0] = v.x; fe[i * 4 + 1] = v.y;
                fe[i * 4 + 2] = v.z; fe[i * 4 + 3] = v.w;
            }
#pragma unroll
            for (int c = 0; c < 20; c++) s_f[e * 28 + c] = to_tf32(fe[c]);
            s_rc[e] = rcut[e0 + e];
            s_ii[e] = idx_i[e0 + e];
            s_jj[e] = idx_j[e0 + e];
        }
        __syncthreads();

        // ---- Phase B: t = ssp(f@Wf1 + bf1) via tf32 MMA; split bf16 -> A tiles ----
        {
            uint32_t fa[3][4];
#pragma unroll
            for (int k0 = 0; k0 < 3; k0++) {
                int c = k0 * 8 + tg;
                fa[k0][0] = __float_as_uint(s_f[(m0 + g) * 28 + c]);
                fa[k0][1] = __float_as_uint(s_f[(m0 + g + 8) * 28 + c]);
                fa[k0][2] = __float_as_uint(s_f[(m0 + g) * 28 + c + 4]);
                fa[k0][3] = __float_as_uint(s_f[(m0 + g + 8) * 28 + c + 4]);
            }
#pragma unroll
            for (int np = 0; np < 16; np++) {
                int c = np * 8 + 2 * tg;
                float b0v = s_bf1[c], b1v = s_bf1[c + 1];
                float a1[4] = {b0v, b1v, b0v, b1v};
#pragma unroll
                for (int k0 = 0; k0 < 3; k0++) {
                    int kr = k0 * 8 + tg;
                    uint32_t wb0 = __float_as_uint(s_Wf1[kr * 136 + np * 8 + g]);
                    uint32_t wb1 = __float_as_uint(s_Wf1[(kr + 4) * 136 + np * 8 + g]);
                    mma_tf32(a1, fa[k0], wb0, wb1);
                }
                // epilogue: ssp + hi/lo split into A tiles
                float x0 = sspf(a1[0]), x1 = sspf(a1[1]);
                float x2 = sspf(a1[2]), x3 = sspf(a1[3]);
                uint32_t off0 = (uint32_t)((m0 + g) * 272 + np * 16 + tg * 4);
                uint32_t off1 = (uint32_t)((m0 + g + 8) * 272 + np * 16 + tg * 4);
                split_store(s_Ahi, s_Alo, off0, x0, x1);
                split_store(s_Ahi, s_Alo, off1, x2, x3);
            }
        }
        __syncthreads();

        // ---- Phase C: Wij = 3-pass bf16 HMMA ----
        float acc[8][2][4];
        hmma3(sbase + OFF_AHI, sbase + OFF_ALO, sbase + OFF_BHI, sbase + OFF_BLO,
              m0, lane, acc);
        __syncthreads();   // all A/B reads done before wij overwrites A

        {
            int r0 = m0 + g, r1 = m0 + g + 8;
            float rc0 = s_rc[r0], rc1 = s_rc[r1];
            float* w0 = s_wij + r0 * 132;
            float* w1 = s_wij + r1 * 132;
#pragma unroll
            for (int np = 0; np < 8; np++) {
                int c0 = np * 16 + 2 * tg, c1 = c0 + 8;
                float b00 = s_bf2[c0], b01 = s_bf2[c0 + 1];
                float b10 = s_bf2[c1], b11 = s_bf2[c1 + 1];
                *reinterpret_cast<float2*>(w0 + c0) =
                    make_float2((acc[np][0][0] + b00) * rc0, (acc[np][0][1] + b01) * rc0);
                *reinterpret_cast<float2*>(w0 + c1) =
                    make_float2((acc[np][1][0] + b10) * rc0, (acc[np][1][1] + b11) * rc0);
                *reinterpret_cast<float2*>(w1 + c0) =
                    make_float2((acc[np][0][2] + b00) * rc1, (acc[np][0][3] + b01) * rc1);
                *reinterpret_cast<float2*>(w1 + c1) =
                    make_float2((acc[np][1][2] + b10) * rc1, (acc[np][1][3] + b11) * rc1);
            }
        }
        __syncthreads();

        // ---- Phase D: batched gather h[idx_j]*wij, vector-red into agg[idx_i] ----
        {
            int q = tid & 31;
            int w = tid >> 5;
            int jj[16], ii[16];
#pragma unroll
            for (int b = 0; b < 16; b++) {
                jj[b] = s_jj[w + 8 * b];
                ii[b] = s_ii[w + 8 * b];
            }
#pragma unroll
            for (int h2 = 0; h2 < 2; h2++) {
                float4 hv[8];
#pragma unroll
                for (int b = 0; b < 8; b++)
                    hv[b] = __ldg(reinterpret_cast<const float4*>(g_h) +
                                  (size_t)jj[h2 * 8 + b] * 32 + q);
#pragma unroll
                for (int b = 0; b < 8; b++) {
                    int e = w + 8 * (h2 * 8 + b);
                    float4 wv = *reinterpret_cast<const float4*>(s_wij + e * 132 + q * 4);
                    float* ap = g_agg + (size_t)ii[h2 * 8 + b] * NF + q * 4;
                    red4(ap, hv[b].x * wv.x, hv[b].y * wv.y, hv[b].z * wv.z, hv[b].w * wv.w);
                }
            }
        }
    }
}

// ================= Kernel 3: out = ssp(agg@Wo1+bo1)@Wo2 + bo2 =================
#define OUT_AHI  0
#define OUT_ALO  34816
#define OUT_B1HI 69632
#define OUT_B1LO 104448
#define OUT_B2HI 139264
#define OUT_B2LO 174080
#define OUT_B1   208896
#define OUT_B2   209408
#define OUT_SMEM 209920

__global__ __launch_bounds__(256, 1)
void k_out(const float* __restrict__ Wo1, const float* __restrict__ bo1,
           const float* __restrict__ Wo2, const float* __restrict__ bo2,
           float* __restrict__ out) {
    extern __shared__ __align__(1024) char sm[];
    float* s_b1 = reinterpret_cast<float*>(sm + OUT_B1);
    float* s_b2 = reinterpret_cast<float*>(sm + OUT_B2);
    int tid = threadIdx.x, wid = tid >> 5, lane = tid & 31;
    int m0 = wid * 16;
    int g = lane >> 2, tg = lane & 3;
    int row0 = blockIdx.x * 128;
    uint32_t sbase = smem_u32(sm);

    // weights (transposed, split)
    for (int i = tid; i < 16384; i += 256) {
        int n = i >> 7, k = i & 127;
        uint32_t o = (uint32_t)(n * 136 + k) * 2u;
        float w1 = Wo1[k * NF + n];
        __nv_bfloat16 h1 = __float2bfloat16(w1);
        *reinterpret_cast<__nv_bfloat16*>(sm + OUT_B1HI + o) = h1;
        *reinterpret_cast<__nv_bfloat16*>(sm + OUT_B1LO + o) = __float2bfloat16(w1 - __bfloat162float(h1));
        float w2 = Wo2[k * NF + n];
        __nv_bfloat16 h2 = __float2bfloat16(w2);
        *reinterpret_cast<__nv_bfloat16*>(sm + OUT_B2HI + o) = h2;
        *reinterpret_cast<__nv_bfloat16*>(sm + OUT_B2LO + o) = __float2bfloat16(w2 - __bfloat162float(h2));
    }
    // agg tile split -> A
    for (int i = tid; i < 16384; i += 256) {
        int r = i >> 7, c = i & 127;
        float v = (row0 + r < N_ATOMS) ? g_agg[(size_t)(row0 + r) * NF + c] : 0.f;
        __nv_bfloat16 h = __float2bfloat16(v);
        uint32_t o = (uint32_t)(r * 136 + c) * 2u;
        *reinterpret_cast<__nv_bfloat16*>(sm + OUT_AHI + o) = h;
        *reinterpret_cast<__nv_bfloat16*>(sm + OUT_ALO + o) = __float2bfloat16(v - __bfloat162float(h));
    }
    if (tid < 128) { s_b1[tid] = bo1[tid]; s_b2[tid] = bo2[tid]; }
    __syncthreads();

    float acc[8][2][4];
    hmma3(sbase + OUT_AHI, sbase + OUT_ALO, sbase + OUT_B1HI, sbase + OUT_B1LO,
          m0, lane, acc);
    __syncthreads();   // all A reads done before overwrite

    // u = ssp(acc + bo1) -> split back into A tiles
    {
        int r0 = m0 + g, r1 = m0 + g + 8;
#pragma unroll
        for (int np = 0; np < 8; np++) {
            int c0 = np * 16 + 2 * tg, c1 = c0 + 8;
            float u00 = sspf(acc[np][0][0] + s_b1[c0]);
            float u01 = sspf(acc[np][0][1] + s_b1[c0 + 1]);
            float u10 = sspf(acc[np][1][0] + s_b1[c1]);
            float u11 = sspf(acc[np][1][1] + s_b1[c1 + 1]);
            float u02 = sspf(acc[np][0][2] + s_b1[c0]);
            float u03 = sspf(acc[np][0][3] + s_b1[c0 + 1]);
            float u12 = sspf(acc[np][1][2] + s_b1[c1]);
            float u13 = sspf(acc[np][1][3] + s_b1[c1 + 1]);
            split_store(sm + OUT_AHI, sm + OUT_ALO, (uint32_t)(r0 * 272 + c0 * 2), u00, u01);
            split_store(sm + OUT_AHI, sm + OUT_ALO, (uint32_t)(r0 * 272 + c1 * 2), u10, u11);
            split_store(sm + OUT_AHI, sm + OUT_ALO, (uint32_t)(r1 * 272 + c0 * 2), u02, u03);
            split_store(sm + OUT_AHI, sm + OUT_ALO, (uint32_t)(r1 * 272 + c1 * 2), u12, u13);
        }
    }
    __syncthreads();

    float acc2[8][2][4];
    hmma3(sbase + OUT_AHI, sbase + OUT_ALO, sbase + OUT_B2HI, sbase + OUT_B2LO,
          m0, lane, acc2);

    int r0 = row0 + m0 + g, r1 = r0 + 8;
#pragma unroll
    for (int np = 0; np < 8; np++) {
        int c0 = np * 16 + 2 * tg, c1 = c0 + 8;
        if (r0 < N_ATOMS) {
            *reinterpret_cast<float2*>(out + (size_t)r0 * NF + c0) =
                make_float2(acc2[np][0][0] + s_b2[c0], acc2[np][0][1] + s_b2[c0 + 1]);
            *reinterpret_cast<float2*>(out + (size_t)r0 * NF + c1) =
                make_float2(acc2[np][1][0] + s_b2[c1], acc2[np][1][1] + s_b2[c1 + 1]);
        }
        if (r1 < N_ATOMS) {
            *reinterpret_cast<float2*>(out + (size_t)r1 * NF + c0) =
                make_float2(acc2[np][0][2] + s_b2[c0], acc2[np][0][3] + s_b2[c0 + 1]);
            *reinterpret_cast<float2*>(out + (size_t)r1 * NF + c1) =
                make_float2(acc2[np][1][2] + s_b2[c1], acc2[np][1][3] + s_b2[c1 + 1]);
        }
    }
}

// ================= launch =================
extern "C" void kernel_launch(void* const* d_in, const int* in_sizes, int n_in,
                              void* d_out, int out_size) {
    const float* x     = (const float*)d_in[0];
    const float* f_ij  = (const float*)d_in[1];
    const float* rcut  = (const float*)d_in[2];
    const float* W_in  = (const float*)d_in[3];
    const float* b_in  = (const float*)d_in[4];
    const float* Wf1   = (const float*)d_in[5];
    const float* bf1   = (const float*)d_in[6];
    const float* Wf2   = (const float*)d_in[7];
    const float* bf2   = (const float*)d_in[8];
    const float* Wo1   = (const float*)d_in[9];
    const float* bo1   = (const float*)d_in[10];
    const float* Wo2   = (const float*)d_in[11];
    const float* bo2   = (const float*)d_in[12];
    const int*   idx_i = (const int*)d_in[13];
    const int*   idx_j = (const int*)d_in[14];
    float* out = (float*)d_out;

    cudaFuncSetAttribute(k_embed, cudaFuncAttributeMaxDynamicSharedMemorySize, EMB_SMEM);
    cudaFuncSetAttribute(k_edge,  cudaFuncAttributeMaxDynamicSharedMemorySize, EDGE_SMEM);
    cudaFuncSetAttribute(k_out,   cudaFuncAttributeMaxDynamicSharedMemorySize, OUT_SMEM);

    int nsm = 148;
    cudaDeviceGetAttribute(&nsm, cudaDevAttrMultiProcessorCount, 0);
    int node_blocks = (N_ATOMS + 127) / 128;   // 391

    k_embed<<<node_blocks, 256, EMB_SMEM>>>(x, W_in, b_in);
    k_edge<<<nsm, 256, EDGE_SMEM>>>(f_ij, rcut, Wf1, bf1, Wf2, bf2, idx_i, idx_j);
    k_out<<<node_blocks, 256, OUT_SMEM>>>(Wo1, bo1, Wo2, bo2, out);
}

// round 8
// speedup vs baseline: 2.6469x; 1.0487x over previous
#include <cuda_runtime.h>
#include <cuda_bf16.h>
#include <cstdint>

#define N_ATOMS   50000
#define N_PAIRS   1600000
#define NF        128
#define N_RBF     20
#define E_TILE    128
#define N_TILES   (N_PAIRS / E_TILE)   // 12500
#define LOG2F_C   0.69314718055994530942f

typedef unsigned long long u64;

// ---------------- scratch ----------------
__device__ float g_h[N_ATOMS * NF];
__device__ float g_agg[N_ATOMS * NF];

// ---------------- helpers ----------------
__device__ __forceinline__ uint32_t smem_u32(const void* p) {
    uint32_t a;
    asm("{ .reg .u64 t; cvta.to.shared.u64 t, %1; cvt.u32.u64 %0, t; }" : "=r"(a) : "l"(p));
    return a;
}
__device__ __forceinline__ float sspf(float x) {
    float e = __expf(-fabsf(x));
    return fmaxf(x, 0.0f) + __logf(1.0f + e) - LOG2F_C;
}
__device__ __forceinline__ void red4(float* p, float a, float b, float c, float d) {
    asm volatile("red.global.add.v4.f32 [%0], {%1,%2,%3,%4};"
                 :: "l"(p), "f"(a), "f"(b), "f"(c), "f"(d) : "memory");
}
__device__ __forceinline__ float to_tf32(float x) {
    uint32_t u; asm("cvt.rna.tf32.f32 %0, %1;" : "=r"(u) : "f"(x));
    return __uint_as_float(u);
}
__device__ __forceinline__ uint32_t pack_bf16(float x0, float x1) {
    uint32_t u; asm("cvt.rn.bf16x2.f32 %0, %1, %2;" : "=r"(u) : "f"(x1), "f"(x0));
    return u;
}

// ---------------- MMA primitives ----------------
__device__ __forceinline__ void ldmx4(uint32_t r[4], uint32_t addr) {
    asm volatile("ldmatrix.sync.aligned.m8n8.x4.shared.b16 {%0,%1,%2,%3}, [%4];"
                 : "=r"(r[0]), "=r"(r[1]), "=r"(r[2]), "=r"(r[3]) : "r"(addr));
}
__device__ __forceinline__ void mma16816(float d[4], const uint32_t a[4],
                                         uint32_t b0, uint32_t b1) {
    asm volatile(
        "mma.sync.aligned.m16n8k16.row.col.f32.bf16.bf16.f32 "
        "{%0,%1,%2,%3}, {%4,%5,%6,%7}, {%8,%9}, {%0,%1,%2,%3};"
        : "+f"(d[0]), "+f"(d[1]), "+f"(d[2]), "+f"(d[3])
        : "r"(a[0]), "r"(a[1]), "r"(a[2]), "r"(a[3]), "r"(b0), "r"(b1));
}
__device__ __forceinline__ void mma_tf32(float d[4], const uint32_t a[4],
                                         uint32_t b0, uint32_t b1) {
    asm volatile(
        "mma.sync.aligned.m16n8k8.row.col.f32.tf32.tf32.f32 "
        "{%0,%1,%2,%3}, {%4,%5,%6,%7}, {%8,%9}, {%0,%1,%2,%3};"
        : "+f"(d[0]), "+f"(d[1]), "+f"(d[2]), "+f"(d[3])
        : "r"(a[0]), "r"(a[1]), "r"(a[2]), "r"(a[3]), "r"(b0), "r"(b1));
}

// ---------------- 3-pass bf16 HMMA, half-width per warp ----------------
// A/B tiles: [128][136] bf16 (272 B rows). Warp covers rows m0..m0+15,
// col blocks n0..n0+3 (each 16 cols). acc[4][2][4].
__device__ __forceinline__ void hmma3h(uint32_t aAhi, uint32_t aAlo,
                                       uint32_t aBhi, uint32_t aBlo,
                                       int m0, int n0, int lane, float acc[4][2][4]) {
    int lr = lane & 15;
    int lc = (lane >> 4) * 8;
    uint32_t ah[8][4], al[8][4];
    uint32_t rowb = (uint32_t)((m0 + lr) * 272);
#pragma unroll
    for (int k = 0; k < 8; k++) {
        uint32_t cb = (uint32_t)(k * 16 + lc) * 2u;
        ldmx4(ah[k], aAhi + rowb + cb);
        ldmx4(al[k], aAlo + rowb + cb);
    }
#pragma unroll
    for (int jn = 0; jn < 4; jn++) {
        int np = n0 + jn;
#pragma unroll
        for (int h = 0; h < 2; h++)
#pragma unroll
            for (int j = 0; j < 4; j++) acc[jn][h][j] = 0.f;
        uint32_t nrow = (uint32_t)((np * 16 + lr) * 272);
#pragma unroll
        for (int k = 0; k < 8; k++) {
            uint32_t cb = (uint32_t)(k * 16 + lc) * 2u;
            uint32_t bh[4], bl[4];
            ldmx4(bh, aBhi + nrow + cb);
            ldmx4(bl, aBlo + nrow + cb);
            mma16816(acc[jn][0], ah[k], bh[0], bh[2]);
            mma16816(acc[jn][0], al[k], bh[0], bh[2]);
            mma16816(acc[jn][0], ah[k], bl[0], bl[2]);
            mma16816(acc[jn][1], ah[k], bh[1], bh[3]);
            mma16816(acc[jn][1], al[k], bh[1], bh[3]);
            mma16816(acc[jn][1], ah[k], bl[1], bl[3]);
        }
    }
}

__device__ __forceinline__ void split_store(char* hi, char* lo, uint32_t off,
                                            float x0, float x1) {
    uint32_t uh = pack_bf16(x0, x1);
    float h0 = __uint_as_float(uh << 16);
    float h1 = __uint_as_float(uh & 0xFFFF0000u);
    uint32_t ul = pack_bf16(x0 - h0, x1 - h1);
    *reinterpret_cast<uint32_t*>(hi + off) = uh;
    *reinterpret_cast<uint32_t*>(lo + off) = ul;
}

// ================= Kernel 1: h = x@W_in + b_in ; zero agg =================
#define EMB_AHI 0
#define EMB_ALO 34816
#define EMB_BHI 69632
#define EMB_BLO 104448
#define EMB_B   139264
#define EMB_SMEM (EMB_B + 512)

__global__ __launch_bounds__(512, 1)
void k_embed(const float* __restrict__ x, const float* __restrict__ W_in,
             const float* __restrict__ b_in) {
    extern __shared__ __align__(1024) char sm[];
    float* s_b = reinterpret_cast<float*>(sm + EMB_B);
    int tid = threadIdx.x, wid = tid >> 5, lane = tid & 31;
    int mw = (wid >> 1) * 16, ch = wid & 1;
    int row0 = blockIdx.x * 128;
    uint32_t sbase = smem_u32(sm);

    for (int i = tid; i < 16384; i += 512) {
        int n = i >> 7, k = i & 127;
        float w = W_in[k * NF + n];
        __nv_bfloat16 h = __float2bfloat16(w);
        uint32_t o = (uint32_t)(n * 136 + k) * 2u;
        *reinterpret_cast<__nv_bfloat16*>(sm + EMB_BHI + o) = h;
        *reinterpret_cast<__nv_bfloat16*>(sm + EMB_BLO + o) = __float2bfloat16(w - __bfloat162float(h));
    }
    for (int i = tid; i < 16384; i += 512) {
        int r = i >> 7, c = i & 127;
        float v = (row0 + r < N_ATOMS) ? x[(size_t)(row0 + r) * NF + c] : 0.f;
        __nv_bfloat16 h = __float2bfloat16(v);
        uint32_t o = (uint32_t)(r * 136 + c) * 2u;
        *reinterpret_cast<__nv_bfloat16*>(sm + EMB_AHI + o) = h;
        *reinterpret_cast<__nv_bfloat16*>(sm + EMB_ALO + o) = __float2bfloat16(v - __bfloat162float(h));
    }
    if (tid < 128) s_b[tid] = b_in[tid];
    __syncthreads();

    float acc[4][2][4];
    hmma3h(sbase + EMB_AHI, sbase + EMB_ALO, sbase + EMB_BHI, sbase + EMB_BLO,
           mw, ch * 4, lane, acc);

    int g = lane >> 2, tg = lane & 3;
    int r0 = row0 + mw + g, r1 = r0 + 8;
    float2 z2 = make_float2(0.f, 0.f);
#pragma unroll
    for (int jn = 0; jn < 4; jn++) {
        int np = ch * 4 + jn;
        int c0 = np * 16 + 2 * tg, c1 = c0 + 8;
        if (r0 < N_ATOMS) {
            *reinterpret_cast<float2*>(g_h + (size_t)r0 * NF + c0) =
                make_float2(acc[jn][0][0] + s_b[c0], acc[jn][0][1] + s_b[c0 + 1]);
            *reinterpret_cast<float2*>(g_h + (size_t)r0 * NF + c1) =
                make_float2(acc[jn][1][0] + s_b[c1], acc[jn][1][1] + s_b[c1 + 1]);
            *reinterpret_cast<float2*>(g_agg + (size_t)r0 * NF + c0) = z2;
            *reinterpret_cast<float2*>(g_agg + (size_t)r0 * NF + c1) = z2;
        }
        if (r1 < N_ATOMS) {
            *reinterpret_cast<float2*>(g_h + (size_t)r1 * NF + c0) =
                make_float2(acc[jn][0][2] + s_b[c0], acc[jn][0][3] + s_b[c0 + 1]);
            *reinterpret_cast<float2*>(g_h + (size_t)r1 * NF + c1) =
                make_float2(acc[jn][1][2] + s_b[c1], acc[jn][1][3] + s_b[c1 + 1]);
            *reinterpret_cast<float2*>(g_agg + (size_t)r1 * NF + c0) = z2;
            *reinterpret_cast<float2*>(g_agg + (size_t)r1 * NF + c1) = z2;
        }
    }
}

// ================= Kernel 2: persistent edge kernel =================
#define OFF_AHI   0
#define OFF_ALO   34816
#define OFF_WIJ   0                    // aliases A tiles (67584 <= 69632)
#define OFF_BHI   69632
#define OFF_BLO   104448
#define OFF_F     139264               // [128][28] f32
#define OFF_WF1   153600               // [24][136] f32
#define OFF_BF1   166656
#define OFF_BF2   167168
#define OFF_RC    167680
#define OFF_II    168192
#define OFF_JJ    168704
#define EDGE_SMEM 169216

__global__ __launch_bounds__(512, 1)
void k_edge(const float* __restrict__ f_ij, const float* __restrict__ rcut,
            const float* __restrict__ Wf1, const float* __restrict__ bf1,
            const float* __restrict__ Wf2, const float* __restrict__ bf2,
            const int* __restrict__ idx_i, const int* __restrict__ idx_j) {
    extern __shared__ __align__(1024) char sm[];
    char*  s_Ahi = sm + OFF_AHI;
    char*  s_Alo = sm + OFF_ALO;
    float* s_wij = reinterpret_cast<float*>(sm + OFF_WIJ);
    float* s_f   = reinterpret_cast<float*>(sm + OFF_F);
    float* s_Wf1 = reinterpret_cast<float*>(sm + OFF_WF1);
    float* s_bf1 = reinterpret_cast<float*>(sm + OFF_BF1);
    float* s_bf2 = reinterpret_cast<float*>(sm + OFF_BF2);
    float* s_rc  = reinterpret_cast<float*>(sm + OFF_RC);
    int*   s_ii  = reinterpret_cast<int*>(sm + OFF_II);
    int*   s_jj  = reinterpret_cast<int*>(sm + OFF_JJ);

    int tid = threadIdx.x, wid = tid >> 5, lane = tid & 31;
    int mw = (wid >> 1) * 16, ch = wid & 1;
    int g = lane >> 2, tg = lane & 3;
    uint32_t sbase = smem_u32(sm);

    // ---- one-time init ----
    for (int i = tid; i < 3584; i += 512) s_f[i] = 0.f;
    for (int i = tid; i < 3264; i += 512) s_Wf1[i] = 0.f;
    __syncthreads();
    for (int i = tid; i < 2560; i += 512) {
        int k = i >> 7, n = i & 127;
        s_Wf1[k * 136 + n] = to_tf32(Wf1[i]);
    }
    for (int i = tid; i < 16384; i += 512) {
        int n = i >> 7, k = i & 127;
        float w = Wf2[k * NF + n];
        __nv_bfloat16 h = __float2bfloat16(w);
        uint32_t o = (uint32_t)(n * 136 + k) * 2u;
        *reinterpret_cast<__nv_bfloat16*>(sm + OFF_BHI + o) = h;
        *reinterpret_cast<__nv_bfloat16*>(sm + OFF_BLO + o) = __float2bfloat16(w - __bfloat162float(h));
    }
    if (tid < 128) { s_bf1[tid] = bf1[tid]; s_bf2[tid] = bf2[tid]; }
    __syncthreads();

    for (int t = blockIdx.x; t < N_TILES; t += gridDim.x) {
        __syncthreads();   // prev tile phase D fully done
        int e0 = t * E_TILE;

        // ---- Phase A: edge data ----
        if (tid < 128) {
            int e = tid;
            const float4* fp = reinterpret_cast<const float4*>(f_ij + (size_t)(e0 + e) * 20);
            float fe[20];
#pragma unroll
            for (int i = 0; i < 5; i++) {
                float4 v = fp[i];
                fe[i * 4 + 0] = v.x; fe[i * 4 + 1] = v.y;
                fe[i * 4 + 2] = v.z; fe[i * 4 + 3] = v.w;
            }
#pragma unroll
            for (int c = 0; c < 20; c++) s_f[e * 28 + c] = to_tf32(fe[c]);
            s_rc[e] = rcut[e0 + e];
            s_ii[e] = idx_i[e0 + e];
            s_jj[e] = idx_j[e0 + e];
        }
        __syncthreads();

        // ---- Phase B: t = ssp(f@Wf1 + bf1) via tf32 MMA; split bf16 -> A tiles ----
        {
            uint32_t fa[3][4];
#pragma unroll
            for (int k0 = 0; k0 < 3; k0++) {
                int c = k0 * 8 + tg;
                fa[k0][0] = __float_as_uint(s_f[(mw + g) * 28 + c]);
                fa[k0][1] = __float_as_uint(s_f[(mw + g + 8) * 28 + c]);
                fa[k0][2] = __float_as_uint(s_f[(mw + g) * 28 + c + 4]);
                fa[k0][3] = __float_as_uint(s_f[(mw + g + 8) * 28 + c + 4]);
            }
#pragma unroll
            for (int np2 = 0; np2 < 8; np2++) {
                int c = ch * 64 + np2 * 8 + 2 * tg;
                float b0v = s_bf1[c], b1v = s_bf1[c + 1];
                float a1[4] = {b0v, b1v, b0v, b1v};
#pragma unroll
                for (int k0 = 0; k0 < 3; k0++) {
                    int kr = k0 * 8 + tg;
                    uint32_t wb0 = __float_as_uint(s_Wf1[kr * 136 + ch * 64 + np2 * 8 + g]);
                    uint32_t wb1 = __float_as_uint(s_Wf1[(kr + 4) * 136 + ch * 64 + np2 * 8 + g]);
                    mma_tf32(a1, fa[k0], wb0, wb1);
                }
                float x0 = sspf(a1[0]), x1 = sspf(a1[1]);
                float x2 = sspf(a1[2]), x3 = sspf(a1[3]);
                uint32_t off0 = (uint32_t)((mw + g) * 272 + ch * 128 + np2 * 16 + tg * 4);
                uint32_t off1 = (uint32_t)((mw + g + 8) * 272 + ch * 128 + np2 * 16 + tg * 4);
                split_store(s_Ahi, s_Alo, off0, x0, x1);
                split_store(s_Ahi, s_Alo, off1, x2, x3);
            }
        }
        __syncthreads();

        // ---- Phase C: Wij = 3-pass bf16 HMMA (per warp: 16 rows x 64 cols) ----
        float acc[4][2][4];
        hmma3h(sbase + OFF_AHI, sbase + OFF_ALO, sbase + OFF_BHI, sbase + OFF_BLO,
               mw, ch * 4, lane, acc);
        __syncthreads();   // all A/B reads done before wij overwrites A

        {
            int r0 = mw + g, r1 = mw + g + 8;
            float rc0 = s_rc[r0], rc1 = s_rc[r1];
            float* w0 = s_wij + r0 * 132;
            float* w1 = s_wij + r1 * 132;
#pragma unroll
            for (int jn = 0; jn < 4; jn++) {
                int np = ch * 4 + jn;
                int c0 = np * 16 + 2 * tg, c1 = c0 + 8;
                float b00 = s_bf2[c0], b01 = s_bf2[c0 + 1];
                float b10 = s_bf2[c1], b11 = s_bf2[c1 + 1];
                *reinterpret_cast<float2*>(w0 + c0) =
                    make_float2((acc[jn][0][0] + b00) * rc0, (acc[jn][0][1] + b01) * rc0);
                *reinterpret_cast<float2*>(w0 + c1) =
                    make_float2((acc[jn][1][0] + b10) * rc0, (acc[jn][1][1] + b11) * rc0);
                *reinterpret_cast<float2*>(w1 + c0) =
                    make_float2((acc[jn][0][2] + b00) * rc1, (acc[jn][0][3] + b01) * rc1);
                *reinterpret_cast<float2*>(w1 + c1) =
                    make_float2((acc[jn][1][2] + b10) * rc1, (acc[jn][1][3] + b11) * rc1);
            }
        }
        __syncthreads();

        // ---- Phase D: batched gather h[idx_j]*wij -> red into agg[idx_i] ----
        {
            int q = lane;
            int jj[8], ii[8];
#pragma unroll
            for (int b = 0; b < 8; b++) {
                jj[b] = s_jj[wid + 16 * b];
                ii[b] = s_ii[wid + 16 * b];
            }
            float4 hv[8];
#pragma unroll
            for (int b = 0; b < 8; b++)
                hv[b] = __ldg(reinterpret_cast<const float4*>(g_h) + (size_t)jj[b] * 32 + q);
#pragma unroll
            for (int b = 0; b < 8; b++) {
                int e = wid + 16 * b;
                float4 wv = *reinterpret_cast<const float4*>(s_wij + e * 132 + q * 4);
                float* ap = g_agg + (size_t)ii[b] * NF + q * 4;
                red4(ap, hv[b].x * wv.x, hv[b].y * wv.y, hv[b].z * wv.z, hv[b].w * wv.w);
            }
        }
    }
}

// ================= Kernel 3: out = ssp(agg@Wo1+bo1)@Wo2 + bo2 =================
#define OUT_AHI  0
#define OUT_ALO  34816
#define OUT_B1HI 69632
#define OUT_B1LO 104448
#define OUT_B2HI 139264
#define OUT_B2LO 174080
#define OUT_B1   208896
#define OUT_B2   209408
#define OUT_SMEM 209920

__global__ __launch_bounds__(512, 1)
void k_out(const float* __restrict__ Wo1, const float* __restrict__ bo1,
           const float* __restrict__ Wo2, const float* __restrict__ bo2,
           float* __restrict__ out) {
    extern __shared__ __align__(1024) char sm[];
    float* s_b1 = reinterpret_cast<float*>(sm + OUT_B1);
    float* s_b2 = reinterpret_cast<float*>(sm + OUT_B2);
    int tid = threadIdx.x, wid = tid >> 5, lane = tid & 31;
    int mw = (wid >> 1) * 16, ch = wid & 1;
    int g = lane >> 2, tg = lane & 3;
    int row0 = blockIdx.x * 128;
    uint32_t sbase = smem_u32(sm);

    for (int i = tid; i < 16384; i += 512) {
        int n = i >> 7, k = i & 127;
        uint32_t o = (uint32_t)(n * 136 + k) * 2u;
        float w1 = Wo1[k * NF + n];
        __nv_bfloat16 h1 = __float2bfloat16(w1);
        *reinterpret_cast<__nv_bfloat16*>(sm + OUT_B1HI + o) = h1;
        *reinterpret_cast<__nv_bfloat16*>(sm + OUT_B1LO + o) = __float2bfloat16(w1 - __bfloat162float(h1));
        float w2 = Wo2[k * NF + n];
        __nv_bfloat16 h2 = __float2bfloat16(w2);
        *reinterpret_cast<__nv_bfloat16*>(sm + OUT_B2HI + o) = h2;
        *reinterpret_cast<__nv_bfloat16*>(sm + OUT_B2LO + o) = __float2bfloat16(w2 - __bfloat162float(h2));
    }
    for (int i = tid; i < 16384; i += 512) {
        int r = i >> 7, c = i & 127;
        float v = (row0 + r < N_ATOMS) ? g_agg[(size_t)(row0 + r) * NF + c] : 0.f;
        __nv_bfloat16 h = __float2bfloat16(v);
        uint32_t o = (uint32_t)(r * 136 + c) * 2u;
        *reinterpret_cast<__nv_bfloat16*>(sm + OUT_AHI + o) = h;
        *reinterpret_cast<__nv_bfloat16*>(sm + OUT_ALO + o) = __float2bfloat16(v - __bfloat162float(h));
    }
    if (tid < 128) { s_b1[tid] = bo1[tid]; s_b2[tid] = bo2[tid]; }
    __syncthreads();

    float acc[4][2][4];
    hmma3h(sbase + OUT_AHI, sbase + OUT_ALO, sbase + OUT_B1HI, sbase + OUT_B1LO,
           mw, ch * 4, lane, acc);
    __syncthreads();   // all A reads done before overwrite

    {
        int r0 = mw + g, r1 = mw + g + 8;
#pragma unroll
        for (int jn = 0; jn < 4; jn++) {
            int np = ch * 4 + jn;
            int c0 = np * 16 + 2 * tg, c1 = c0 + 8;
            float u00 = sspf(acc[jn][0][0] + s_b1[c0]);
            float u01 = sspf(acc[jn][0][1] + s_b1[c0 + 1]);
            float u10 = sspf(acc[jn][1][0] + s_b1[c1]);
            float u11 = sspf(acc[jn][1][1] + s_b1[c1 + 1]);
            float u02 = sspf(acc[jn][0][2] + s_b1[c0]);
            float u03 = sspf(acc[jn][0][3] + s_b1[c0 + 1]);
            float u12 = sspf(acc[jn][1][2] + s_b1[c1]);
            float u13 = sspf(acc[jn][1][3] + s_b1[c1 + 1]);
            split_store(sm + OUT_AHI, sm + OUT_ALO, (uint32_t)(r0 * 272 + c0 * 2), u00, u01);
            split_store(sm + OUT_AHI, sm + OUT_ALO, (uint32_t)(r0 * 272 + c1 * 2), u10, u11);
            split_store(sm + OUT_AHI, sm + OUT_ALO, (uint32_t)(r1 * 272 + c0 * 2), u02, u03);
            split_store(sm + OUT_AHI, sm + OUT_ALO, (uint32_t)(r1 * 272 + c1 * 2), u12, u13);
        }
    }
    __syncthreads();

    float acc2[4][2][4];
    hmma3h(sbase + OUT_AHI, sbase + OUT_ALO, sbase + OUT_B2HI, sbase + OUT_B2LO,
           mw, ch * 4, lane, acc2);

    int r0 = row0 + mw + g, r1 = r0 + 8;
#pragma unroll
    for (int jn = 0; jn < 4; jn++) {
        int np = ch * 4 + jn;
        int c0 = np * 16 + 2 * tg, c1 = c0 + 8;
        if (r0 < N_ATOMS) {
            *reinterpret_cast<float2*>(out + (size_t)r0 * NF + c0) =
                make_float2(acc2[jn][0][0] + s_b2[c0], acc2[jn][0][1] + s_b2[c0 + 1]);
            *reinterpret_cast<float2*>(out + (size_t)r0 * NF + c1) =
                make_float2(acc2[jn][1][0] + s_b2[c1], acc2[jn][1][1] + s_b2[c1 + 1]);
        }
        if (r1 < N_ATOMS) {
            *reinterpret_cast<float2*>(out + (size_t)r1 * NF + c0) =
                make_float2(acc2[jn][0][2] + s_b2[c0], acc2[jn][0][3] + s_b2[c0 + 1]);
            *reinterpret_cast<float2*>(out + (size_t)r1 * NF + c1) =
                make_float2(acc2[jn][1][2] + s_b2[c1], acc2[jn][1][3] + s_b2[c1 + 1]);
        }
    }
}

// ================= launch =================
extern "C" void kernel_launch(void* const* d_in, const int* in_sizes, int n_in,
                              void* d_out, int out_size) {
    const float* x     = (const float*)d_in[0];
    const float* f_ij  = (const float*)d_in[1];
    const float* rcut  = (const float*)d_in[2];
    const float* W_in  = (const float*)d_in[3];
    const float* b_in  = (const float*)d_in[4];
    const float* Wf1   = (const float*)d_in[5];
    const float* bf1   = (const float*)d_in[6];
    const float* Wf2   = (const float*)d_in[7];
    const float* bf2   = (const float*)d_in[8];
    const float* Wo1   = (const float*)d_in[9];
    const float* bo1   = (const float*)d_in[10];
    const float* Wo2   = (const float*)d_in[11];
    const float* bo2   = (const float*)d_in[12];
    const int*   idx_i = (const int*)d_in[13];
    const int*   idx_j = (const int*)d_in[14];
    float* out = (float*)d_out;

    cudaFuncSetAttribute(k_embed, cudaFuncAttributeMaxDynamicSharedMemorySize, EMB_SMEM);
    cudaFuncSetAttribute(k_edge,  cudaFuncAttributeMaxDynamicSharedMemorySize, EDGE_SMEM);
    cudaFuncSetAttribute(k_out,   cudaFuncAttributeMaxDynamicSharedMemorySize, OUT_SMEM);

    int nsm = 148;
    cudaDeviceGetAttribute(&nsm, cudaDevAttrMultiProcessorCount, 0);
    int node_blocks = (N_ATOMS + 127) / 128;   // 391

    k_embed<<<node_blocks, 512, EMB_SMEM>>>(x, W_in, b_in);
    k_edge<<<nsm, 512, EDGE_SMEM>>>(f_ij, rcut, Wf1, bf1, Wf2, bf2, idx_i, idx_j);
    k_out<<<node_blocks, 512, OUT_SMEM>>>(Wo1, bo1, Wo2, bo2, out);
}

// round 9
// speedup vs baseline: 3.4558x; 1.3056x over previous
#include <cuda_runtime.h>
#include <cuda_bf16.h>
#include <cuda_fp16.h>
#include <cstdint>

#define N_ATOMS   50000
#define N_PAIRS   1600000
#define NF        128
#define N_RBF     20
#define E_TILE    128
#define N_TILES   (N_PAIRS / E_TILE)   // 12500
#define NODE_TILES ((N_ATOMS + 127) / 128)  // 391
#define LOG2F_C   0.69314718055994530942f

typedef unsigned long long u64;

// ---------------- scratch ----------------
__device__ float g_h[N_ATOMS * NF];
__device__ float g_agg[N_ATOMS * NF];

// ---------------- helpers ----------------
__device__ __forceinline__ uint32_t smem_u32(const void* p) {
    uint32_t a;
    asm("{ .reg .u64 t; cvta.to.shared.u64 t, %1; cvt.u32.u64 %0, t; }" : "=r"(a) : "l"(p));
    return a;
}
__device__ __forceinline__ float sspf(float x) {
    float e = __expf(-fabsf(x));
    return fmaxf(x, 0.0f) + __logf(1.0f + e) - LOG2F_C;
}
__device__ __forceinline__ void red4(float* p, float a, float b, float c, float d) {
    asm volatile("red.global.add.v4.f32 [%0], {%1,%2,%3,%4};"
                 :: "l"(p), "f"(a), "f"(b), "f"(c), "f"(d) : "memory");
}
__device__ __forceinline__ float to_tf32(float x) {
    uint32_t u; asm("cvt.rna.tf32.f32 %0, %1;" : "=r"(u) : "f"(x));
    return __uint_as_float(u);
}
__device__ __forceinline__ uint32_t pack_bf16(float x0, float x1) {
    uint32_t u; asm("cvt.rn.bf16x2.f32 %0, %1, %2;" : "=r"(u) : "f"(x1), "f"(x0));
    return u;
}

// ---------------- MMA primitives ----------------
__device__ __forceinline__ void ldmx4(uint32_t r[4], uint32_t addr) {
    asm volatile("ldmatrix.sync.aligned.m8n8.x4.shared.b16 {%0,%1,%2,%3}, [%4];"
                 : "=r"(r[0]), "=r"(r[1]), "=r"(r[2]), "=r"(r[3]) : "r"(addr));
}
__device__ __forceinline__ void mma16816(float d[4], const uint32_t a[4],
                                         uint32_t b0, uint32_t b1) {
    asm volatile(
        "mma.sync.aligned.m16n8k16.row.col.f32.bf16.bf16.f32 "
        "{%0,%1,%2,%3}, {%4,%5,%6,%7}, {%8,%9}, {%0,%1,%2,%3};"
        : "+f"(d[0]), "+f"(d[1]), "+f"(d[2]), "+f"(d[3])
        : "r"(a[0]), "r"(a[1]), "r"(a[2]), "r"(a[3]), "r"(b0), "r"(b1));
}
__device__ __forceinline__ void mmaf16(float d[4], const uint32_t a[4],
                                       uint32_t b0, uint32_t b1) {
    asm volatile(
        "mma.sync.aligned.m16n8k16.row.col.f32.f16.f16.f32 "
        "{%0,%1,%2,%3}, {%4,%5,%6,%7}, {%8,%9}, {%0,%1,%2,%3};"
        : "+f"(d[0]), "+f"(d[1]), "+f"(d[2]), "+f"(d[3])
        : "r"(a[0]), "r"(a[1]), "r"(a[2]), "r"(a[3]), "r"(b0), "r"(b1));
}
__device__ __forceinline__ void mma_tf32(float d[4], const uint32_t a[4],
                                         uint32_t b0, uint32_t b1) {
    asm volatile(
        "mma.sync.aligned.m16n8k8.row.col.f32.tf32.tf32.f32 "
        "{%0,%1,%2,%3}, {%4,%5,%6,%7}, {%8,%9}, {%0,%1,%2,%3};"
        : "+f"(d[0]), "+f"(d[1]), "+f"(d[2]), "+f"(d[3])
        : "r"(a[0]), "r"(a[1]), "r"(a[2]), "r"(a[3]), "r"(b0), "r"(b1));
}

// ---------------- 3-pass bf16 HMMA (node kernels) ----------------
// A/B tiles: [128][136] bf16 (272 B rows). Warp: rows m0..m0+15, col blocks n0..n0+3.
__device__ __forceinline__ void hmma3h(uint32_t aAhi, uint32_t aAlo,
                                       uint32_t aBhi, uint32_t aBlo,
                                       int m0, int n0, int lane, float acc[4][2][4]) {
    int lr = lane & 15;
    int lc = (lane >> 4) * 8;
    uint32_t ah[8][4], al[8][4];
    uint32_t rowb = (uint32_t)((m0 + lr) * 272);
#pragma unroll
    for (int k = 0; k < 8; k++) {
        uint32_t cb = (uint32_t)(k * 16 + lc) * 2u;
        ldmx4(ah[k], aAhi + rowb + cb);
        ldmx4(al[k], aAlo + rowb + cb);
    }
#pragma unroll
    for (int jn = 0; jn < 4; jn++) {
        int np = n0 + jn;
#pragma unroll
        for (int h = 0; h < 2; h++)
#pragma unroll
            for (int j = 0; j < 4; j++) acc[jn][h][j] = 0.f;
        uint32_t nrow = (uint32_t)((np * 16 + lr) * 272);
#pragma unroll
        for (int k = 0; k < 8; k++) {
            uint32_t cb = (uint32_t)(k * 16 + lc) * 2u;
            uint32_t bh[4], bl[4];
            ldmx4(bh, aBhi + nrow + cb);
            ldmx4(bl, aBlo + nrow + cb);
            mma16816(acc[jn][0], ah[k], bh[0], bh[2]);
            mma16816(acc[jn][0], al[k], bh[0], bh[2]);
            mma16816(acc[jn][0], ah[k], bl[0], bl[2]);
            mma16816(acc[jn][1], ah[k], bh[1], bh[3]);
            mma16816(acc[jn][1], al[k], bh[1], bh[3]);
            mma16816(acc[jn][1], ah[k], bl[1], bl[3]);
        }
    }
}

// ---------------- 2-pass fp16 HMMA (edge GEMM): A split hi/lo, B single ----------------
__device__ __forceinline__ void hmma2f(uint32_t aAhi, uint32_t aAlo, uint32_t aB,
                                       int m0, int n0, int lane, float acc[4][2][4]) {
    int lr = lane & 15;
    int lc = (lane >> 4) * 8;
    uint32_t ah[8][4], al[8][4];
    uint32_t rowb = (uint32_t)((m0 + lr) * 272);
#pragma unroll
    for (int k = 0; k < 8; k++) {
        uint32_t cb = (uint32_t)(k * 16 + lc) * 2u;
        ldmx4(ah[k], aAhi + rowb + cb);
        ldmx4(al[k], aAlo + rowb + cb);
    }
#pragma unroll
    for (int jn = 0; jn < 4; jn++) {
        int np = n0 + jn;
#pragma unroll
        for (int h = 0; h < 2; h++)
#pragma unroll
            for (int j = 0; j < 4; j++) acc[jn][h][j] = 0.f;
        uint32_t nrow = (uint32_t)((np * 16 + lr) * 272);
#pragma unroll
        for (int k = 0; k < 8; k++) {
            uint32_t cb = (uint32_t)(k * 16 + lc) * 2u;
            uint32_t bh[4];
            ldmx4(bh, aB + nrow + cb);
            mmaf16(acc[jn][0], ah[k], bh[0], bh[2]);
            mmaf16(acc[jn][0], al[k], bh[0], bh[2]);
            mmaf16(acc[jn][1], ah[k], bh[1], bh[3]);
            mmaf16(acc[jn][1], al[k], bh[1], bh[3]);
        }
    }
}

// splits
__device__ __forceinline__ void split_store(char* hi, char* lo, uint32_t off,
                                            float x0, float x1) {
    uint32_t uh = pack_bf16(x0, x1);
    float h0 = __uint_as_float(uh << 16);
    float h1 = __uint_as_float(uh & 0xFFFF0000u);
    uint32_t ul = pack_bf16(x0 - h0, x1 - h1);
    *reinterpret_cast<uint32_t*>(hi + off) = uh;
    *reinterpret_cast<uint32_t*>(lo + off) = ul;
}
__device__ __forceinline__ void split_store_f16(char* hi, char* lo, uint32_t off,
                                                float x0, float x1) {
    uint32_t uh; asm("cvt.rn.f16x2.f32 %0, %1, %2;" : "=r"(uh) : "f"(x1), "f"(x0));
    __half2 hh = *reinterpret_cast<__half2*>(&uh);
    float h0 = __low2float(hh), h1 = __high2float(hh);
    uint32_t ul; asm("cvt.rn.f16x2.f32 %0, %1, %2;" : "=r"(ul) : "f"(x1 - h1), "f"(x0 - h0));
    *reinterpret_cast<uint32_t*>(hi + off) = uh;
    *reinterpret_cast<uint32_t*>(lo + off) = ul;
}

// ================= Kernel 1: persistent h = x@W_in + b_in ; zero agg =================
#define EMB_BHI 0
#define EMB_BLO 34816
#define EMB_A0  69632          // buf0: hi 34816 + lo 34816
#define EMB_A1  139264         // buf1
#define EMB_B   208896
#define EMB_SMEM (EMB_B + 512)

__global__ __launch_bounds__(512, 1)
void k_embed(const float* __restrict__ x, const float* __restrict__ W_in,
             const float* __restrict__ b_in) {
    extern __shared__ __align__(1024) char sm[];
    float* s_b = reinterpret_cast<float*>(sm + EMB_B);
    int tid = threadIdx.x, wid = tid >> 5, lane = tid & 31;
    int mw = (wid >> 1) * 16, ch = wid & 1;
    int g = lane >> 2, tg = lane & 3;
    uint32_t sbase = smem_u32(sm);

    // one-time: W_in^T split (coalesced read, transposed STS)
    for (int i = tid; i < 16384; i += 512) {
        int k = i >> 7, n = i & 127;
        float w = W_in[i];
        __nv_bfloat16 h = __float2bfloat16(w);
        uint32_t o = (uint32_t)(n * 136 + k) * 2u;
        *reinterpret_cast<__nv_bfloat16*>(sm + EMB_BHI + o) = h;
        *reinterpret_cast<__nv_bfloat16*>(sm + EMB_BLO + o) = __float2bfloat16(w - __bfloat162float(h));
    }
    if (tid < 128) s_b[tid] = b_in[tid];

    int p = 0;
    for (int t = blockIdx.x; t < NODE_TILES; t += gridDim.x) {
        int row0 = t * 128;
        // load x tile to regs (coalesced)
        float4 xr[8];
#pragma unroll
        for (int j = 0; j < 8; j++) {
            int i4 = j * 512 + tid;
            int r = i4 >> 5;
            xr[j] = (row0 + r < N_ATOMS)
                ? __ldg(reinterpret_cast<const float4*>(x) + (size_t)(row0 + r) * 32 + (i4 & 31))
                : make_float4(0.f, 0.f, 0.f, 0.f);
        }
        char* ahi = sm + (p ? EMB_A1 : EMB_A0);
        char* alo = ahi + 34816;
#pragma unroll
        for (int j = 0; j < 8; j++) {
            int i4 = j * 512 + tid;
            int r = i4 >> 5, q = i4 & 31;
            uint32_t o = (uint32_t)(r * 136 + q * 4) * 2u;
            split_store(ahi, alo, o,     xr[j].x, xr[j].y);
            split_store(ahi, alo, o + 4, xr[j].z, xr[j].w);
        }
        __syncthreads();   // the only barrier per tile (ping-pong buffers)

        float acc[4][2][4];
        uint32_t ab = sbase + (p ? EMB_A1 : EMB_A0);
        hmma3h(ab, ab + 34816, sbase + EMB_BHI, sbase + EMB_BLO, mw, ch * 4, lane, acc);

        int r0 = row0 + mw + g, r1 = r0 + 8;
        float2 z2 = make_float2(0.f, 0.f);
#pragma unroll
        for (int jn = 0; jn < 4; jn++) {
            int np = ch * 4 + jn;
            int c0 = np * 16 + 2 * tg, c1 = c0 + 8;
            if (r0 < N_ATOMS) {
                *reinterpret_cast<float2*>(g_h + (size_t)r0 * NF + c0) =
                    make_float2(acc[jn][0][0] + s_b[c0], acc[jn][0][1] + s_b[c0 + 1]);
                *reinterpret_cast<float2*>(g_h + (size_t)r0 * NF + c1) =
                    make_float2(acc[jn][1][0] + s_b[c1], acc[jn][1][1] + s_b[c1 + 1]);
                *reinterpret_cast<float2*>(g_agg + (size_t)r0 * NF + c0) = z2;
                *reinterpret_cast<float2*>(g_agg + (size_t)r0 * NF + c1) = z2;
            }
            if (r1 < N_ATOMS) {
                *reinterpret_cast<float2*>(g_h + (size_t)r1 * NF + c0) =
                    make_float2(acc[jn][0][2] + s_b[c0], acc[jn][0][3] + s_b[c0 + 1]);
                *reinterpret_cast<float2*>(g_h + (size_t)r1 * NF + c1) =
                    make_float2(acc[jn][1][2] + s_b[c1], acc[jn][1][3] + s_b[c1 + 1]);
                *reinterpret_cast<float2*>(g_agg + (size_t)r1 * NF + c0) = z2;
                *reinterpret_cast<float2*>(g_agg + (size_t)r1 * NF + c1) = z2;
            }
        }
        p ^= 1;
    }
}

// ================= Kernel 2: persistent edge kernel (fp16 2-pass) =================
#define OFF_AHI   0            // fp16 hi  34816
#define OFF_ALO   34816        // fp16 lo  34816
#define OFF_B     69632        // fp16 Wf2 34816
#define OFF_WIJ   104448       // 128*132 f32 = 67584
#define OFF_F     172032       // [128][28] f32
#define OFF_WF1   186368       // [24][136] f32
#define OFF_BF1   199424
#define OFF_BF2   199936
#define OFF_RC    200448
#define OFF_II    200960
#define OFF_JJ    201472
#define EDGE_SMEM 201984

__global__ __launch_bounds__(512, 1)
void k_edge(const float* __restrict__ f_ij, const float* __restrict__ rcut,
            const float* __restrict__ Wf1, const float* __restrict__ bf1,
            const float* __restrict__ Wf2, const float* __restrict__ bf2,
            const int* __restrict__ idx_i, const int* __restrict__ idx_j) {
    extern __shared__ __align__(1024) char sm[];
    char*  s_Ahi = sm + OFF_AHI;
    char*  s_Alo = sm + OFF_ALO;
    float* s_wij = reinterpret_cast<float*>(sm + OFF_WIJ);
    float* s_f   = reinterpret_cast<float*>(sm + OFF_F);
    float* s_Wf1 = reinterpret_cast<float*>(sm + OFF_WF1);
    float* s_bf1 = reinterpret_cast<float*>(sm + OFF_BF1);
    float* s_bf2 = reinterpret_cast<float*>(sm + OFF_BF2);
    float* s_rc  = reinterpret_cast<float*>(sm + OFF_RC);
    int*   s_ii  = reinterpret_cast<int*>(sm + OFF_II);
    int*   s_jj  = reinterpret_cast<int*>(sm + OFF_JJ);

    int tid = threadIdx.x, wid = tid >> 5, lane = tid & 31;
    int mw = (wid >> 1) * 16, ch = wid & 1;
    int g = lane >> 2, tg = lane & 3;
    uint32_t sbase = smem_u32(sm);

    // ---- one-time init ----
    for (int i = tid; i < 3584; i += 512) s_f[i] = 0.f;
    for (int i = tid; i < 3264; i += 512) s_Wf1[i] = 0.f;
    __syncthreads();
    for (int i = tid; i < 2560; i += 512) {
        int k = i >> 7, n = i & 127;
        s_Wf1[k * 136 + n] = to_tf32(Wf1[i]);
    }
    for (int i = tid; i < 16384; i += 512) {
        int k = i >> 7, n = i & 127;   // coalesced read of Wf2
        uint32_t o = (uint32_t)(n * 136 + k) * 2u;
        *reinterpret_cast<__half*>(sm + OFF_B + o) = __float2half_rn(Wf2[i]);
    }
    if (tid < 128) { s_bf1[tid] = bf1[tid]; s_bf2[tid] = bf2[tid]; }
    __syncthreads();

    for (int t = blockIdx.x; t < N_TILES; t += gridDim.x) {
        __syncthreads();   // phase D of prev tile done before overwriting edge data
        int e0 = t * E_TILE;

        // ---- Phase A: edge data ----
        if (tid < 128) {
            int e = tid;
            const float4* fp = reinterpret_cast<const float4*>(f_ij + (size_t)(e0 + e) * 20);
            float fe[20];
#pragma unroll
            for (int i = 0; i < 5; i++) {
                float4 v = fp[i];
                fe[i * 4 + 0] = v.x; fe[i * 4 + 1] = v.y;
                fe[i * 4 + 2] = v.z; fe[i * 4 + 3] = v.w;
            }
#pragma unroll
            for (int c = 0; c < 20; c++) s_f[e * 28 + c] = to_tf32(fe[c]);
            s_rc[e] = rcut[e0 + e];
            s_ii[e] = idx_i[e0 + e];
            s_jj[e] = idx_j[e0 + e];
        }
        __syncthreads();

        // ---- Phase B: t = ssp(f@Wf1 + bf1) via tf32 MMA; split fp16 -> A tiles ----
        {
            uint32_t fa[3][4];
#pragma unroll
            for (int k0 = 0; k0 < 3; k0++) {
                int c = k0 * 8 + tg;
                fa[k0][0] = __float_as_uint(s_f[(mw + g) * 28 + c]);
                fa[k0][1] = __float_as_uint(s_f[(mw + g + 8) * 28 + c]);
                fa[k0][2] = __float_as_uint(s_f[(mw + g) * 28 + c + 4]);
                fa[k0][3] = __float_as_uint(s_f[(mw + g + 8) * 28 + c + 4]);
            }
#pragma unroll
            for (int np2 = 0; np2 < 8; np2++) {
                int c = ch * 64 + np2 * 8 + 2 * tg;
                float b0v = s_bf1[c], b1v = s_bf1[c + 1];
                float a1[4] = {b0v, b1v, b0v, b1v};
#pragma unroll
                for (int k0 = 0; k0 < 3; k0++) {
                    int kr = k0 * 8 + tg;
                    uint32_t wb0 = __float_as_uint(s_Wf1[kr * 136 + ch * 64 + np2 * 8 + g]);
                    uint32_t wb1 = __float_as_uint(s_Wf1[(kr + 4) * 136 + ch * 64 + np2 * 8 + g]);
                    mma_tf32(a1, fa[k0], wb0, wb1);
                }
                float x0 = sspf(a1[0]), x1 = sspf(a1[1]);
                float x2 = sspf(a1[2]), x3 = sspf(a1[3]);
                uint32_t off0 = (uint32_t)((mw + g) * 272 + ch * 128 + np2 * 16 + tg * 4);
                uint32_t off1 = (uint32_t)((mw + g + 8) * 272 + ch * 128 + np2 * 16 + tg * 4);
                split_store_f16(s_Ahi, s_Alo, off0, x0, x1);
                split_store_f16(s_Ahi, s_Alo, off1, x2, x3);
            }
        }
        __syncthreads();

        // ---- Phase C: Wij via 2-pass fp16 HMMA ----
        float acc[4][2][4];
        hmma2f(sbase + OFF_AHI, sbase + OFF_ALO, sbase + OFF_B, mw, ch * 4, lane, acc);

        // epilogue: bias + rcut -> s_wij (separate region, no barrier needed first)
        {
            int r0 = mw + g, r1 = mw + g + 8;
            float rc0 = s_rc[r0], rc1 = s_rc[r1];
            float* w0 = s_wij + r0 * 132;
            float* w1 = s_wij + r1 * 132;
#pragma unroll
            for (int jn = 0; jn < 4; jn++) {
                int np = ch * 4 + jn;
                int c0 = np * 16 + 2 * tg, c1 = c0 + 8;
                float b00 = s_bf2[c0], b01 = s_bf2[c0 + 1];
                float b10 = s_bf2[c1], b11 = s_bf2[c1 + 1];
                *reinterpret_cast<float2*>(w0 + c0) =
                    make_float2((acc[jn][0][0] + b00) * rc0, (acc[jn][0][1] + b01) * rc0);
                *reinterpret_cast<float2*>(w0 + c1) =
                    make_float2((acc[jn][1][0] + b10) * rc0, (acc[jn][1][1] + b11) * rc0);
                *reinterpret_cast<float2*>(w1 + c0) =
                    make_float2((acc[jn][0][2] + b00) * rc1, (acc[jn][0][3] + b01) * rc1);
                *reinterpret_cast<float2*>(w1 + c1) =
                    make_float2((acc[jn][1][2] + b10) * rc1, (acc[jn][1][3] + b11) * rc1);
            }
        }
        __syncthreads();

        // ---- Phase D: batched gather h[idx_j]*wij -> red into agg[idx_i] ----
        {
            int q = lane;
            int jj[8], ii[8];
#pragma unroll
            for (int b = 0; b < 8; b++) {
                jj[b] = s_jj[wid + 16 * b];
                ii[b] = s_ii[wid + 16 * b];
            }
            float4 hv[8];
#pragma unroll
            for (int b = 0; b < 8; b++)
                hv[b] = __ldg(reinterpret_cast<const float4*>(g_h) + (size_t)jj[b] * 32 + q);
#pragma unroll
            for (int b = 0; b < 8; b++) {
                int e = wid + 16 * b;
                float4 wv = *reinterpret_cast<const float4*>(s_wij + e * 132 + q * 4);
                float* ap = g_agg + (size_t)ii[b] * NF + q * 4;
                red4(ap, hv[b].x * wv.x, hv[b].y * wv.y, hv[b].z * wv.z, hv[b].w * wv.w);
            }
        }
    }
}

// ================= Kernel 3: persistent out = ssp(agg@Wo1+bo1)@Wo2 + bo2 =================
#define OUT_B1HI 0
#define OUT_B1LO 34816
#define OUT_B2HI 69632
#define OUT_B2LO 104448
#define OUT_AHI  139264
#define OUT_ALO  174080
#define OUT_B1   208896
#define OUT_B2   209408
#define OUT_SMEM 209920

__global__ __launch_bounds__(512, 1)
void k_out(const float* __restrict__ Wo1, const float* __restrict__ bo1,
           const float* __restrict__ Wo2, const float* __restrict__ bo2,
           float* __restrict__ out) {
    extern __shared__ __align__(1024) char sm[];
    float* s_b1 = reinterpret_cast<float*>(sm + OUT_B1);
    float* s_b2 = reinterpret_cast<float*>(sm + OUT_B2);
    int tid = threadIdx.x, wid = tid >> 5, lane = tid & 31;
    int mw = (wid >> 1) * 16, ch = wid & 1;
    int g = lane >> 2, tg = lane & 3;
    uint32_t sbase = smem_u32(sm);

    // one-time weights (coalesced reads)
    for (int i = tid; i < 16384; i += 512) {
        int k = i >> 7, n = i & 127;
        uint32_t o = (uint32_t)(n * 136 + k) * 2u;
        float w1 = Wo1[i];
        __nv_bfloat16 h1 = __float2bfloat16(w1);
        *reinterpret_cast<__nv_bfloat16*>(sm + OUT_B1HI + o) = h1;
        *reinterpret_cast<__nv_bfloat16*>(sm + OUT_B1LO + o) = __float2bfloat16(w1 - __bfloat162float(h1));
        float w2 = Wo2[i];
        __nv_bfloat16 h2 = __float2bfloat16(w2);
        *reinterpret_cast<__nv_bfloat16*>(sm + OUT_B2HI + o) = h2;
        *reinterpret_cast<__nv_bfloat16*>(sm + OUT_B2LO + o) = __float2bfloat16(w2 - __bfloat162float(h2));
    }
    if (tid < 128) { s_b1[tid] = bo1[tid]; s_b2[tid] = bo2[tid]; }

    for (int t = blockIdx.x; t < NODE_TILES; t += gridDim.x) {
        int row0 = t * 128;
        // load agg tile, split -> A
        float4 ar[8];
#pragma unroll
        for (int j = 0; j < 8; j++) {
            int i4 = j * 512 + tid;
            int r = i4 >> 5;
            ar[j] = (row0 + r < N_ATOMS)
                ? __ldg(reinterpret_cast<const float4*>(g_agg) + (size_t)(row0 + r) * 32 + (i4 & 31))
                : make_float4(0.f, 0.f, 0.f, 0.f);
        }
#pragma unroll
        for (int j = 0; j < 8; j++) {
            int i4 = j * 512 + tid;
            int r = i4 >> 5, q = i4 & 31;
            uint32_t o = (uint32_t)(r * 136 + q * 4) * 2u;
            split_store(sm + OUT_AHI, sm + OUT_ALO, o,     ar[j].x, ar[j].y);
            split_store(sm + OUT_AHI, sm + OUT_ALO, o + 4, ar[j].z, ar[j].w);
        }
        __syncthreads();

        float acc[4][2][4];
        hmma3h(sbase + OUT_AHI, sbase + OUT_ALO, sbase + OUT_B1HI, sbase + OUT_B1LO,
               mw, ch * 4, lane, acc);
        __syncthreads();   // all A reads done before ssp overwrite

        {
            int r0 = mw + g, r1 = mw + g + 8;
#pragma unroll
            for (int jn = 0; jn < 4; jn++) {
                int np = ch * 4 + jn;
                int c0 = np * 16 + 2 * tg, c1 = c0 + 8;
                float u00 = sspf(acc[jn][0][0] + s_b1[c0]);
                float u01 = sspf(acc[jn][0][1] + s_b1[c0 + 1]);
                float u10 = sspf(acc[jn][1][0] + s_b1[c1]);
                float u11 = sspf(acc[jn][1][1] + s_b1[c1 + 1]);
                float u02 = sspf(acc[jn][0][2] + s_b1[c0]);
                float u03 = sspf(acc[jn][0][3] + s_b1[c0 + 1]);
                float u12 = sspf(acc[jn][1][2] + s_b1[c1]);
                float u13 = sspf(acc[jn][1][3] + s_b1[c1 + 1]);
                split_store(sm + OUT_AHI, sm + OUT_ALO, (uint32_t)(r0 * 272 + c0 * 2), u00, u01);
                split_store(sm + OUT_AHI, sm + OUT_ALO, (uint32_t)(r0 * 272 + c1 * 2), u10, u11);
                split_store(sm + OUT_AHI, sm + OUT_ALO, (uint32_t)(r1 * 272 + c0 * 2), u02, u03);
                split_store(sm + OUT_AHI, sm + OUT_ALO, (uint32_t)(r1 * 272 + c1 * 2), u12, u13);
            }
        }
        __syncthreads();

        float acc2[4][2][4];
        hmma3h(sbase + OUT_AHI, sbase + OUT_ALO, sbase + OUT_B2HI, sbase + OUT_B2LO,
               mw, ch * 4, lane, acc2);

        int r0 = row0 + mw + g, r1 = r0 + 8;
#pragma unroll
        for (int jn = 0; jn < 4; jn++) {
            int np = ch * 4 + jn;
            int c0 = np * 16 + 2 * tg, c1 = c0 + 8;
            if (r0 < N_ATOMS) {
                *reinterpret_cast<float2*>(out + (size_t)r0 * NF + c0) =
                    make_float2(acc2[jn][0][0] + s_b2[c0], acc2[jn][0][1] + s_b2[c0 + 1]);
                *reinterpret_cast<float2*>(out + (size_t)r0 * NF + c1) =
                    make_float2(acc2[jn][1][0] + s_b2[c1], acc2[jn][1][1] + s_b2[c1 + 1]);
            }
            if (r1 < N_ATOMS) {
                *reinterpret_cast<float2*>(out + (size_t)r1 * NF + c0) =
                    make_float2(acc2[jn][0][2] + s_b2[c0], acc2[jn][0][3] + s_b2[c0 + 1]);
                *reinterpret_cast<float2*>(out + (size_t)r1 * NF + c1) =
                    make_float2(acc2[jn][1][2] + s_b2[c1], acc2[jn][1][3] + s_b2[c1 + 1]);
            }
        }
        __syncthreads();   // A reads done before next tile's split stores
    }
}

// ================= launch =================
extern "C" void kernel_launch(void* const* d_in, const int* in_sizes, int n_in,
                              void* d_out, int out_size) {
    const float* x     = (const float*)d_in[0];
    const float* f_ij  = (const float*)d_in[1];
    const float* rcut  = (const float*)d_in[2];
    const float* W_in  = (const float*)d_in[3];
    const float* b_in  = (const float*)d_in[4];
    const float* Wf1   = (const float*)d_in[5];
    const float* bf1   = (const float*)d_in[6];
    const float* Wf2   = (const float*)d_in[7];
    const float* bf2   = (const float*)d_in[8];
    const float* Wo1   = (const float*)d_in[9];
    const float* bo1   = (const float*)d_in[10];
    const float* Wo2   = (const float*)d_in[11];
    const float* bo2   = (const float*)d_in[12];
    const int*   idx_i = (const int*)d_in[13];
    const int*   idx_j = (const int*)d_in[14];
    float* out = (float*)d_out;

    cudaFuncSetAttribute(k_embed, cudaFuncAttributeMaxDynamicSharedMemorySize, EMB_SMEM);
    cudaFuncSetAttribute(k_edge,  cudaFuncAttributeMaxDynamicSharedMemorySize, EDGE_SMEM);
    cudaFuncSetAttribute(k_out,   cudaFuncAttributeMaxDynamicSharedMemorySize, OUT_SMEM);

    int nsm = 148;
    cudaDeviceGetAttribute(&nsm, cudaDevAttrMultiProcessorCount, 0);

    k_embed<<<nsm, 512, EMB_SMEM>>>(x, W_in, b_in);
    k_edge<<<nsm, 512, EDGE_SMEM>>>(f_ij, rcut, Wf1, bf1, Wf2, bf2, idx_i, idx_j);
    k_out<<<nsm, 512, OUT_SMEM>>>(Wo1, bo1, Wo2, bo2, out);
}

// round 10
// speedup vs baseline: 3.7981x; 1.0990x over previous
#include <cuda_runtime.h>
#include <cuda_bf16.h>
#include <cuda_fp16.h>
#include <cstdint>

#define N_ATOMS   50000
#define N_PAIRS   1600000
#define NF        128
#define N_RBF     20
#define E_TILE    128
#define N_TILES   (N_PAIRS / E_TILE)   // 12500
#define NODE_TILES ((N_ATOMS + 127) / 128)  // 391
#define LOG2F_C   0.69314718055994530942f

typedef unsigned long long u64;

// ---------------- scratch ----------------
__device__ float g_h[N_ATOMS * NF];
__device__ float g_agg[N_ATOMS * NF];

// ---------------- helpers ----------------
__device__ __forceinline__ uint32_t smem_u32(const void* p) {
    uint32_t a;
    asm("{ .reg .u64 t; cvta.to.shared.u64 t, %1; cvt.u32.u64 %0, t; }" : "=r"(a) : "l"(p));
    return a;
}
__device__ __forceinline__ float sspf(float x) {
    float e = __expf(-fabsf(x));
    return fmaxf(x, 0.0f) + __logf(1.0f + e) - LOG2F_C;
}
__device__ __forceinline__ void red4(float* p, float a, float b, float c, float d) {
    asm volatile("red.global.add.v4.f32 [%0], {%1,%2,%3,%4};"
                 :: "l"(p), "f"(a), "f"(b), "f"(c), "f"(d) : "memory");
}
__device__ __forceinline__ float to_tf32(float x) {
    uint32_t u; asm("cvt.rna.tf32.f32 %0, %1;" : "=r"(u) : "f"(x));
    return __uint_as_float(u);
}
__device__ __forceinline__ uint32_t pack_bf16(float x0, float x1) {
    uint32_t u; asm("cvt.rn.bf16x2.f32 %0, %1, %2;" : "=r"(u) : "f"(x1), "f"(x0));
    return u;
}

// ---------------- MMA primitives ----------------
__device__ __forceinline__ void ldmx4(uint32_t r[4], uint32_t addr) {
    asm volatile("ldmatrix.sync.aligned.m8n8.x4.shared.b16 {%0,%1,%2,%3}, [%4];"
                 : "=r"(r[0]), "=r"(r[1]), "=r"(r[2]), "=r"(r[3]) : "r"(addr));
}
__device__ __forceinline__ void mma16816(float d[4], const uint32_t a[4],
                                         uint32_t b0, uint32_t b1) {
    asm volatile(
        "mma.sync.aligned.m16n8k16.row.col.f32.bf16.bf16.f32 "
        "{%0,%1,%2,%3}, {%4,%5,%6,%7}, {%8,%9}, {%0,%1,%2,%3};"
        : "+f"(d[0]), "+f"(d[1]), "+f"(d[2]), "+f"(d[3])
        : "r"(a[0]), "r"(a[1]), "r"(a[2]), "r"(a[3]), "r"(b0), "r"(b1));
}
__device__ __forceinline__ void mmaf16(float d[4], const uint32_t a[4],
                                       uint32_t b0, uint32_t b1) {
    asm volatile(
        "mma.sync.aligned.m16n8k16.row.col.f32.f16.f16.f32 "
        "{%0,%1,%2,%3}, {%4,%5,%6,%7}, {%8,%9}, {%0,%1,%2,%3};"
        : "+f"(d[0]), "+f"(d[1]), "+f"(d[2]), "+f"(d[3])
        : "r"(a[0]), "r"(a[1]), "r"(a[2]), "r"(a[3]), "r"(b0), "r"(b1));
}
__device__ __forceinline__ void mma_tf32(float d[4], const uint32_t a[4],
                                         uint32_t b0, uint32_t b1) {
    asm volatile(
        "mma.sync.aligned.m16n8k8.row.col.f32.tf32.tf32.f32 "
        "{%0,%1,%2,%3}, {%4,%5,%6,%7}, {%8,%9}, {%0,%1,%2,%3};"
        : "+f"(d[0]), "+f"(d[1]), "+f"(d[2]), "+f"(d[3])
        : "r"(a[0]), "r"(a[1]), "r"(a[2]), "r"(a[3]), "r"(b0), "r"(b1));
}

// ---------------- 3-pass bf16 HMMA (node kernels) ----------------
__device__ __forceinline__ void hmma3h(uint32_t aAhi, uint32_t aAlo,
                                       uint32_t aBhi, uint32_t aBlo,
                                       int m0, int n0, int lane, float acc[4][2][4]) {
    int lr = lane & 15;
    int lc = (lane >> 4) * 8;
    uint32_t ah[8][4], al[8][4];
    uint32_t rowb = (uint32_t)((m0 + lr) * 272);
#pragma unroll
    for (int k = 0; k < 8; k++) {
        uint32_t cb = (uint32_t)(k * 16 + lc) * 2u;
        ldmx4(ah[k], aAhi + rowb + cb);
        ldmx4(al[k], aAlo + rowb + cb);
    }
#pragma unroll
    for (int jn = 0; jn < 4; jn++) {
        int np = n0 + jn;
#pragma unroll
        for (int h = 0; h < 2; h++)
#pragma unroll
            for (int j = 0; j < 4; j++) acc[jn][h][j] = 0.f;
        uint32_t nrow = (uint32_t)((np * 16 + lr) * 272);
#pragma unroll
        for (int k = 0; k < 8; k++) {
            uint32_t cb = (uint32_t)(k * 16 + lc) * 2u;
            uint32_t bh[4], bl[4];
            ldmx4(bh, aBhi + nrow + cb);
            ldmx4(bl, aBlo + nrow + cb);
            mma16816(acc[jn][0], ah[k], bh[0], bh[2]);
            mma16816(acc[jn][0], al[k], bh[0], bh[2]);
            mma16816(acc[jn][0], ah[k], bl[0], bl[2]);
            mma16816(acc[jn][1], ah[k], bh[1], bh[3]);
            mma16816(acc[jn][1], al[k], bh[1], bh[3]);
            mma16816(acc[jn][1], ah[k], bl[1], bl[3]);
        }
    }
}

// ---------------- 2-pass fp16 HMMA, k-halved (lower reg peak) ----------------
__device__ __forceinline__ void hmma2f(uint32_t aAhi, uint32_t aAlo, uint32_t aB,
                                       int m0, int n0, int lane, float acc[4][2][4]) {
    int lr = lane & 15;
    int lc = (lane >> 4) * 8;
#pragma unroll
    for (int jn = 0; jn < 4; jn++)
#pragma unroll
        for (int h = 0; h < 2; h++)
#pragma unroll
            for (int j = 0; j < 4; j++) acc[jn][h][j] = 0.f;

    uint32_t rowb = (uint32_t)((m0 + lr) * 272);
#pragma unroll
    for (int kh = 0; kh < 2; kh++) {
        uint32_t ah[4][4], al[4][4];
#pragma unroll
        for (int k = 0; k < 4; k++) {
            uint32_t cb = (uint32_t)((kh * 4 + k) * 16 + lc) * 2u;
            ldmx4(ah[k], aAhi + rowb + cb);
            ldmx4(al[k], aAlo + rowb + cb);
        }
#pragma unroll
        for (int jn = 0; jn < 4; jn++) {
            int np = n0 + jn;
            uint32_t nrow = (uint32_t)((np * 16 + lr) * 272);
#pragma unroll
            for (int k = 0; k < 4; k++) {
                uint32_t cb = (uint32_t)((kh * 4 + k) * 16 + lc) * 2u;
                uint32_t bh[4];
                ldmx4(bh, aB + nrow + cb);
                mmaf16(acc[jn][0], ah[k], bh[0], bh[2]);
                mmaf16(acc[jn][0], al[k], bh[0], bh[2]);
                mmaf16(acc[jn][1], ah[k], bh[1], bh[3]);
                mmaf16(acc[jn][1], al[k], bh[1], bh[3]);
            }
        }
    }
}

// splits
__device__ __forceinline__ void split_store(char* hi, char* lo, uint32_t off,
                                            float x0, float x1) {
    uint32_t uh = pack_bf16(x0, x1);
    float h0 = __uint_as_float(uh << 16);
    float h1 = __uint_as_float(uh & 0xFFFF0000u);
    uint32_t ul = pack_bf16(x0 - h0, x1 - h1);
    *reinterpret_cast<uint32_t*>(hi + off) = uh;
    *reinterpret_cast<uint32_t*>(lo + off) = ul;
}
__device__ __forceinline__ void split_store_f16(char* hi, char* lo, uint32_t off,
                                                float x0, float x1) {
    uint32_t uh; asm("cvt.rn.f16x2.f32 %0, %1, %2;" : "=r"(uh) : "f"(x1), "f"(x0));
    __half2 hh = *reinterpret_cast<__half2*>(&uh);
    float h0 = __low2float(hh), h1 = __high2float(hh);
    uint32_t ul; asm("cvt.rn.f16x2.f32 %0, %1, %2;" : "=r"(ul) : "f"(x1 - h1), "f"(x0 - h0));
    *reinterpret_cast<uint32_t*>(hi + off) = uh;
    *reinterpret_cast<uint32_t*>(lo + off) = ul;
}

// ================= Kernel 1: persistent h = x@W_in + b_in ; zero agg =================
#define EMB_BHI 0
#define EMB_BLO 34816
#define EMB_A0  69632
#define EMB_A1  139264
#define EMB_B   208896
#define EMB_SMEM (EMB_B + 512)

__global__ __launch_bounds__(512, 1)
void k_embed(const float* __restrict__ x, const float* __restrict__ W_in,
             const float* __restrict__ b_in) {
    extern __shared__ __align__(1024) char sm[];
    float* s_b = reinterpret_cast<float*>(sm + EMB_B);
    int tid = threadIdx.x, wid = tid >> 5, lane = tid & 31;
    int mw = (wid >> 1) * 16, ch = wid & 1;
    int g = lane >> 2, tg = lane & 3;
    uint32_t sbase = smem_u32(sm);

    for (int i = tid; i < 16384; i += 512) {
        int k = i >> 7, n = i & 127;
        float w = W_in[i];
        __nv_bfloat16 h = __float2bfloat16(w);
        uint32_t o = (uint32_t)(n * 136 + k) * 2u;
        *reinterpret_cast<__nv_bfloat16*>(sm + EMB_BHI + o) = h;
        *reinterpret_cast<__nv_bfloat16*>(sm + EMB_BLO + o) = __float2bfloat16(w - __bfloat162float(h));
    }
    if (tid < 128) s_b[tid] = b_in[tid];

    int p = 0;
    for (int t = blockIdx.x; t < NODE_TILES; t += gridDim.x) {
        int row0 = t * 128;
        float4 xr[8];
#pragma unroll
        for (int j = 0; j < 8; j++) {
            int i4 = j * 512 + tid;
            int r = i4 >> 5;
            xr[j] = (row0 + r < N_ATOMS)
                ? __ldg(reinterpret_cast<const float4*>(x) + (size_t)(row0 + r) * 32 + (i4 & 31))
                : make_float4(0.f, 0.f, 0.f, 0.f);
        }
        char* ahi = sm + (p ? EMB_A1 : EMB_A0);
        char* alo = ahi + 34816;
#pragma unroll
        for (int j = 0; j < 8; j++) {
            int i4 = j * 512 + tid;
            int r = i4 >> 5, q = i4 & 31;
            uint32_t o = (uint32_t)(r * 136 + q * 4) * 2u;
            split_store(ahi, alo, o,     xr[j].x, xr[j].y);
            split_store(ahi, alo, o + 4, xr[j].z, xr[j].w);
        }
        __syncthreads();

        float acc[4][2][4];
        uint32_t ab = sbase + (p ? EMB_A1 : EMB_A0);
        hmma3h(ab, ab + 34816, sbase + EMB_BHI, sbase + EMB_BLO, mw, ch * 4, lane, acc);

        int r0 = row0 + mw + g, r1 = r0 + 8;
        float2 z2 = make_float2(0.f, 0.f);
#pragma unroll
        for (int jn = 0; jn < 4; jn++) {
            int np = ch * 4 + jn;
            int c0 = np * 16 + 2 * tg, c1 = c0 + 8;
            if (r0 < N_ATOMS) {
                *reinterpret_cast<float2*>(g_h + (size_t)r0 * NF + c0) =
                    make_float2(acc[jn][0][0] + s_b[c0], acc[jn][0][1] + s_b[c0 + 1]);
                *reinterpret_cast<float2*>(g_h + (size_t)r0 * NF + c1) =
                    make_float2(acc[jn][1][0] + s_b[c1], acc[jn][1][1] + s_b[c1 + 1]);
                *reinterpret_cast<float2*>(g_agg + (size_t)r0 * NF + c0) = z2;
                *reinterpret_cast<float2*>(g_agg + (size_t)r0 * NF + c1) = z2;
            }
            if (r1 < N_ATOMS) {
                *reinterpret_cast<float2*>(g_h + (size_t)r1 * NF + c0) =
                    make_float2(acc[jn][0][2] + s_b[c0], acc[jn][0][3] + s_b[c0 + 1]);
                *reinterpret_cast<float2*>(g_h + (size_t)r1 * NF + c1) =
                    make_float2(acc[jn][1][2] + s_b[c1], acc[jn][1][3] + s_b[c1 + 1]);
                *reinterpret_cast<float2*>(g_agg + (size_t)r1 * NF + c0) = z2;
                *reinterpret_cast<float2*>(g_agg + (size_t)r1 * NF + c1) = z2;
            }
        }
        p ^= 1;
    }
}

// ================= Kernel 2: persistent edge kernel (pipelined) =================
#define OFF_AHI   0            // fp16 hi  34816
#define OFF_ALO   34816        // fp16 lo  34816
#define OFF_B     69632        // fp16 Wf2 34816
#define OFF_WIJ   104448       // 128*132 f32 = 67584
#define OFF_F     172032       // [128][28] f32
#define OFF_WF1   186368       // [24][136] f32
#define OFF_BF1   199424
#define OFF_BF2   199936
#define OFF_RC    200448
#define OFF_II    200960
#define OFF_JJ    201472
#define EDGE_SMEM 201984

__global__ __launch_bounds__(512, 1)
void k_edge(const float* __restrict__ f_ij, const float* __restrict__ rcut,
            const float* __restrict__ Wf1, const float* __restrict__ bf1,
            const float* __restrict__ Wf2, const float* __restrict__ bf2,
            const int* __restrict__ idx_i, const int* __restrict__ idx_j) {
    extern __shared__ __align__(1024) char sm[];
    char*  s_Ahi = sm + OFF_AHI;
    char*  s_Alo = sm + OFF_ALO;
    float* s_wij = reinterpret_cast<float*>(sm + OFF_WIJ);
    float* s_f   = reinterpret_cast<float*>(sm + OFF_F);
    float* s_Wf1 = reinterpret_cast<float*>(sm + OFF_WF1);
    float* s_bf1 = reinterpret_cast<float*>(sm + OFF_BF1);
    float* s_bf2 = reinterpret_cast<float*>(sm + OFF_BF2);
    float* s_rc  = reinterpret_cast<float*>(sm + OFF_RC);
    int*   s_ii  = reinterpret_cast<int*>(sm + OFF_II);
    int*   s_jj  = reinterpret_cast<int*>(sm + OFF_JJ);

    int tid = threadIdx.x, wid = tid >> 5, lane = tid & 31;
    int mw = (wid >> 1) * 16, ch = wid & 1;
    int g = lane >> 2, tg = lane & 3;
    uint32_t sbase = smem_u32(sm);

    // ---- one-time init ----
    for (int i = tid; i < 3584; i += 512) s_f[i] = 0.f;
    for (int i = tid; i < 3264; i += 512) s_Wf1[i] = 0.f;
    __syncthreads();
    for (int i = tid; i < 2560; i += 512) {
        int k = i >> 7, n = i & 127;
        s_Wf1[k * 136 + n] = to_tf32(Wf1[i]);
    }
    for (int i = tid; i < 16384; i += 512) {
        int k = i >> 7, n = i & 127;
        uint32_t o = (uint32_t)(n * 136 + k) * 2u;
        *reinterpret_cast<__half*>(sm + OFF_B + o) = __float2half_rn(Wf2[i]);
    }
    if (tid < 128) { s_bf1[tid] = bf1[tid]; s_bf2[tid] = bf2[tid]; }
    __syncthreads();

    // pipeline registers (scatter operands for the previous tile)
    float4 hv[8];
    int ii_r[8];
    bool have_prev = false;

    for (int t = blockIdx.x; t < N_TILES; t += gridDim.x) {
        int e0 = t * E_TILE;

        // ---- top: prefetch tile-t edge data into regs (LDG issue first) ----
        float fe[20], rc_v; int ii_v, jj_v;
        if (tid < 128) {
            const float4* fp = reinterpret_cast<const float4*>(f_ij + (size_t)(e0 + tid) * 20);
#pragma unroll
            for (int i = 0; i < 5; i++) {
                float4 v = __ldg(fp + i);
                fe[i * 4 + 0] = v.x; fe[i * 4 + 1] = v.y;
                fe[i * 4 + 2] = v.z; fe[i * 4 + 3] = v.w;
            }
            rc_v = __ldg(rcut + e0 + tid);
            ii_v = __ldg(idx_i + e0 + tid);
            jj_v = __ldg(idx_j + e0 + tid);
        }

        // ---- scatter(t-1): overlaps the prefetch LDG latency ----
        if (have_prev) {
            int q = lane;
#pragma unroll
            for (int b = 0; b < 8; b++) {
                int e = wid + 16 * b;
                float4 wv = *reinterpret_cast<const float4*>(s_wij + e * 132 + q * 4);
                float* ap = g_agg + (size_t)ii_r[b] * NF + q * 4;
                red4(ap, hv[b].x * wv.x, hv[b].y * wv.y, hv[b].z * wv.z, hv[b].w * wv.w);
            }
        }

        // ---- store tile-t edge data to smem ----
        if (tid < 128) {
#pragma unroll
            for (int c = 0; c < 20; c++) s_f[tid * 28 + c] = to_tf32(fe[c]);
            s_rc[tid] = rc_v;
            s_ii[tid] = ii_v;
            s_jj[tid] = jj_v;
        }
        __syncthreads();   // bar1: A visible; all scatter reads of s_wij done

        // ---- Phase B: t = ssp(f@Wf1 + bf1) via tf32 MMA; split fp16 -> A tiles ----
        {
            uint32_t fa[3][4];
#pragma unroll
            for (int k0 = 0; k0 < 3; k0++) {
                int c = k0 * 8 + tg;
                fa[k0][0] = __float_as_uint(s_f[(mw + g) * 28 + c]);
                fa[k0][1] = __float_as_uint(s_f[(mw + g + 8) * 28 + c]);
                fa[k0][2] = __float_as_uint(s_f[(mw + g) * 28 + c + 4]);
                fa[k0][3] = __float_as_uint(s_f[(mw + g + 8) * 28 + c + 4]);
            }
#pragma unroll
            for (int np2 = 0; np2 < 8; np2++) {
                int c = ch * 64 + np2 * 8 + 2 * tg;
                float b0v = s_bf1[c], b1v = s_bf1[c + 1];
                float a1[4] = {b0v, b1v, b0v, b1v};
#pragma unroll
                for (int k0 = 0; k0 < 3; k0++) {
                    int kr = k0 * 8 + tg;
                    uint32_t wb0 = __float_as_uint(s_Wf1[kr * 136 + ch * 64 + np2 * 8 + g]);
                    uint32_t wb1 = __float_as_uint(s_Wf1[(kr + 4) * 136 + ch * 64 + np2 * 8 + g]);
                    mma_tf32(a1, fa[k0], wb0, wb1);
                }
                float x0 = sspf(a1[0]), x1 = sspf(a1[1]);
                float x2 = sspf(a1[2]), x3 = sspf(a1[3]);
                uint32_t off0 = (uint32_t)((mw + g) * 272 + ch * 128 + np2 * 16 + tg * 4);
                uint32_t off1 = (uint32_t)((mw + g + 8) * 272 + ch * 128 + np2 * 16 + tg * 4);
                split_store_f16(s_Ahi, s_Alo, off0, x0, x1);
                split_store_f16(s_Ahi, s_Alo, off1, x2, x3);
            }
        }
        __syncthreads();   // bar2: A tiles complete

        // ---- Phase C: Wij via 2-pass fp16 HMMA ----
        float acc[4][2][4];
        hmma2f(sbase + OFF_AHI, sbase + OFF_ALO, sbase + OFF_B, mw, ch * 4, lane, acc);

        // epilogue: bias + rcut -> s_wij
        {
            int r0 = mw + g, r1 = mw + g + 8;
            float rc0 = s_rc[r0], rc1 = s_rc[r1];
            float* w0 = s_wij + r0 * 132;
            float* w1 = s_wij + r1 * 132;
#pragma unroll
            for (int jn = 0; jn < 4; jn++) {
                int np = ch * 4 + jn;
                int c0 = np * 16 + 2 * tg, c1 = c0 + 8;
                float b00 = s_bf2[c0], b01 = s_bf2[c0 + 1];
                float b10 = s_bf2[c1], b11 = s_bf2[c1 + 1];
                *reinterpret_cast<float2*>(w0 + c0) =
                    make_float2((acc[jn][0][0] + b00) * rc0, (acc[jn][0][1] + b01) * rc0);
                *reinterpret_cast<float2*>(w0 + c1) =
                    make_float2((acc[jn][1][0] + b10) * rc0, (acc[jn][1][1] + b11) * rc0);
                *reinterpret_cast<float2*>(w1 + c0) =
                    make_float2((acc[jn][0][2] + b00) * rc1, (acc[jn][0][3] + b01) * rc1);
                *reinterpret_cast<float2*>(w1 + c1) =
                    make_float2((acc[jn][1][2] + b10) * rc1, (acc[jn][1][3] + b11) * rc1);
            }
        }

        // ---- gather(t): issue now, consumed by scatter at next iteration top ----
        {
            int q = lane;
            int jj_g[8];
#pragma unroll
            for (int b = 0; b < 8; b++) {
                jj_g[b] = s_jj[wid + 16 * b];
                ii_r[b] = s_ii[wid + 16 * b];
            }
#pragma unroll
            for (int b = 0; b < 8; b++)
                hv[b] = __ldg(reinterpret_cast<const float4*>(g_h) + (size_t)jj_g[b] * 32 + q);
        }
        __syncthreads();   // bar3: epilogue's s_wij visible for next-iter scatter
        have_prev = true;
    }

    // drain: final tile's scatter
    if (have_prev) {
        int q = lane;
#pragma unroll
        for (int b = 0; b < 8; b++) {
            int e = wid + 16 * b;
            float4 wv = *reinterpret_cast<const float4*>(s_wij + e * 132 + q * 4);
            float* ap = g_agg + (size_t)ii_r[b] * NF + q * 4;
            red4(ap, hv[b].x * wv.x, hv[b].y * wv.y, hv[b].z * wv.z, hv[b].w * wv.w);
        }
    }
}

// ================= Kernel 3: persistent out = ssp(agg@Wo1+bo1)@Wo2 + bo2 =================
#define OUT_B1HI 0
#define OUT_B1LO 34816
#define OUT_B2HI 69632
#define OUT_B2LO 104448
#define OUT_AHI  139264
#define OUT_ALO  174080
#define OUT_B1   208896
#define OUT_B2   209408
#define OUT_SMEM 209920

__global__ __launch_bounds__(512, 1)
void k_out(const float* __restrict__ Wo1, const float* __restrict__ bo1,
           const float* __restrict__ Wo2, const float* __restrict__ bo2,
           float* __restrict__ out) {
    extern __shared__ __align__(1024) char sm[];
    float* s_b1 = reinterpret_cast<float*>(sm + OUT_B1);
    float* s_b2 = reinterpret_cast<float*>(sm + OUT_B2);
    int tid = threadIdx.x, wid = tid >> 5, lane = tid & 31;
    int mw = (wid >> 1) * 16, ch = wid & 1;
    int g = lane >> 2, tg = lane & 3;
    uint32_t sbase = smem_u32(sm);

    for (int i = tid; i < 16384; i += 512) {
        int k = i >> 7, n = i & 127;
        uint32_t o = (uint32_t)(n * 136 + k) * 2u;
        float w1 = Wo1[i];
        __nv_bfloat16 h1 = __float2bfloat16(w1);
        *reinterpret_cast<__nv_bfloat16*>(sm + OUT_B1HI + o) = h1;
        *reinterpret_cast<__nv_bfloat16*>(sm + OUT_B1LO + o) = __float2bfloat16(w1 - __bfloat162float(h1));
        float w2 = Wo2[i];
        __nv_bfloat16 h2 = __float2bfloat16(w2);
        *reinterpret_cast<__nv_bfloat16*>(sm + OUT_B2HI + o) = h2;
        *reinterpret_cast<__nv_bfloat16*>(sm + OUT_B2LO + o) = __float2bfloat16(w2 - __bfloat162float(h2));
    }
    if (tid < 128) { s_b1[tid] = bo1[tid]; s_b2[tid] = bo2[tid]; }

    for (int t = blockIdx.x; t < NODE_TILES; t += gridDim.x) {
        int row0 = t * 128;
        float4 ar[8];
#pragma unroll
        for (int j = 0; j < 8; j++) {
            int i4 = j * 512 + tid;
            int r = i4 >> 5;
            ar[j] = (row0 + r < N_ATOMS)
                ? __ldg(reinterpret_cast<const float4*>(g_agg) + (size_t)(row0 + r) * 32 + (i4 & 31))
                : make_float4(0.f, 0.f, 0.f, 0.f);
        }
#pragma unroll
        for (int j = 0; j < 8; j++) {
            int i4 = j * 512 + tid;
            int r = i4 >> 5, q = i4 & 31;
            uint32_t o = (uint32_t)(r * 136 + q * 4) * 2u;
            split_store(sm + OUT_AHI, sm + OUT_ALO, o,     ar[j].x, ar[j].y);
            split_store(sm + OUT_AHI, sm + OUT_ALO, o + 4, ar[j].z, ar[j].w);
        }
        __syncthreads();

        float acc[4][2][4];
        hmma3h(sbase + OUT_AHI, sbase + OUT_ALO, sbase + OUT_B1HI, sbase + OUT_B1LO,
               mw, ch * 4, lane, acc);
        __syncthreads();

        {
            int r0 = mw + g, r1 = mw + g + 8;
#pragma unroll
            for (int jn = 0; jn < 4; jn++) {
                int np = ch * 4 + jn;
                int c0 = np * 16 + 2 * tg, c1 = c0 + 8;
                float u00 = sspf(acc[jn][0][0] + s_b1[c0]);
                float u01 = sspf(acc[jn][0][1] + s_b1[c0 + 1]);
                float u10 = sspf(acc[jn][1][0] + s_b1[c1]);
                float u11 = sspf(acc[jn][1][1] + s_b1[c1 + 1]);
                float u02 = sspf(acc[jn][0][2] + s_b1[c0]);
                float u03 = sspf(acc[jn][0][3] + s_b1[c0 + 1]);
                float u12 = sspf(acc[jn][1][2] + s_b1[c1]);
                float u13 = sspf(acc[jn][1][3] + s_b1[c1 + 1]);
                split_store(sm + OUT_AHI, sm + OUT_ALO, (uint32_t)(r0 * 272 + c0 * 2), u00, u01);
                split_store(sm + OUT_AHI, sm + OUT_ALO, (uint32_t)(r0 * 272 + c1 * 2), u10, u11);
                split_store(sm + OUT_AHI, sm + OUT_ALO, (uint32_t)(r1 * 272 + c0 * 2), u02, u03);
                split_store(sm + OUT_AHI, sm + OUT_ALO, (uint32_t)(r1 * 272 + c1 * 2), u12, u13);
            }
        }
        __syncthreads();

        float acc2[4][2][4];
        hmma3h(sbase + OUT_AHI, sbase + OUT_ALO, sbase + OUT_B2HI, sbase + OUT_B2LO,
               mw, ch * 4, lane, acc2);

        int r0 = row0 + mw + g, r1 = r0 + 8;
#pragma unroll
        for (int jn = 0; jn < 4; jn++) {
            int np = ch * 4 + jn;
            int c0 = np * 16 + 2 * tg, c1 = c0 + 8;
            if (r0 < N_ATOMS) {
                *reinterpret_cast<float2*>(out + (size_t)r0 * NF + c0) =
                    make_float2(acc2[jn][0][0] + s_b2[c0], acc2[jn][0][1] + s_b2[c0 + 1]);
                *reinterpret_cast<float2*>(out + (size_t)r0 * NF + c1) =
                    make_float2(acc2[jn][1][0] + s_b2[c1], acc2[jn][1][1] + s_b2[c1 + 1]);
            }
            if (r1 < N_ATOMS) {
                *reinterpret_cast<float2*>(out + (size_t)r1 * NF + c0) =
                    make_float2(acc2[jn][0][2] + s_b2[c0], acc2[jn][0][3] + s_b2[c0 + 1]);
                *reinterpret_cast<float2*>(out + (size_t)r1 * NF + c1) =
                    make_float2(acc2[jn][1][2] + s_b2[c1], acc2[jn][1][3] + s_b2[c1 + 1]);
            }
        }
        __syncthreads();
    }
}

// ================= launch =================
extern "C" void kernel_launch(void* const* d_in, const int* in_sizes, int n_in,
                              void* d_out, int out_size) {
    const float* x     = (const float*)d_in[0];
    const float* f_ij  = (const float*)d_in[1];
    const float* rcut  = (const float*)d_in[2];
    const float* W_in  = (const float*)d_in[3];
    const float* b_in  = (const float*)d_in[4];
    const float* Wf1   = (const float*)d_in[5];
    const float* bf1   = (const float*)d_in[6];
    const float* Wf2   = (const float*)d_in[7];
    const float* bf2   = (const float*)d_in[8];
    const float* Wo1   = (const float*)d_in[9];
    const float* bo1   = (const float*)d_in[10];
    const float* Wo2   = (const float*)d_in[11];
    const float* bo2   = (const float*)d_in[12];
    const int*   idx_i = (const int*)d_in[13];
    const int*   idx_j = (const int*)d_in[14];
    float* out = (float*)d_out;

    cudaFuncSetAttribute(k_embed, cudaFuncAttributeMaxDynamicSharedMemorySize, EMB_SMEM);
    cudaFuncSetAttribute(k_edge,  cudaFuncAttributeMaxDynamicSharedMemorySize, EDGE_SMEM);
    cudaFuncSetAttribute(k_out,   cudaFuncAttributeMaxDynamicSharedMemorySize, OUT_SMEM);

    int nsm = 148;
    cudaDeviceGetAttribute(&nsm, cudaDevAttrMultiProcessorCount, 0);

    k_embed<<<nsm, 512, EMB_SMEM>>>(x, W_in, b_in);
    k_edge<<<nsm, 512, EDGE_SMEM>>>(f_ij, rcut, Wf1, bf1, Wf2, bf2, idx_i, idx_j);
    k_out<<<nsm, 512, OUT_SMEM>>>(Wo1, bo1, Wo2, bo2, out);
}